// round 1
// baseline (speedup 1.0000x reference)
#include <cuda_runtime.h>
#include <math.h>

#define Bdim 2
#define Ldim 1024
#define Ddim 1024
#define Hdim 16
#define HDdim 64
#define DFFdim 4096
#define WINv 128
#define DILv 4
#define KLAT 64
#define MMEM 64
#define EPSV 1e-6f

#define BLD (Bdim*Ldim*Ddim)
#define BKD (Bdim*KLAT*Ddim)
#define BMD (Bdim*MMEM*Ddim)

// ---------------- scratch (static device memory; no allocations) -------------
__device__ float g_h[BLD];
__device__ float g_qn[BLD];
__device__ float g_kn[BLD];
__device__ float g_Q[BLD];
__device__ float g_K[BLD];
__device__ float g_V[BLD];
__device__ float g_O[BLD];
__device__ float g_oL[BLD];
__device__ float g_oD[BLD];
__device__ float g_xlat[BLD];
__device__ float g_xmem[BLD];
__device__ float g_x1[BLD];
__device__ float g_hn[BLD];
__device__ float g_S[(size_t)Bdim*Hdim*Ldim*Ldim];     // 128 MB scores
__device__ float g_latprev[BKD];
__device__ float g_lat[BKD];
__device__ float g_latq[BKD];
__device__ float g_latk[BKD];
__device__ float g_memprev[BMD];
__device__ float g_mem[BMD];
__device__ float g_memq[BMD];
__device__ float g_memk[BMD];
__device__ float g_memdelta[BMD];
__device__ float g_u[(size_t)Bdim*Ldim*2*DFFdim];      // 64 MB
__device__ float g_gact[(size_t)Bdim*Ldim*DFFdim];     // 32 MB

// ---------------- rmsnorm: one block per row, D=1024 -------------------------
__global__ void rmsnorm_k(const float* __restrict__ x, const float* __restrict__ w,
                          float* __restrict__ o) {
    int row = blockIdx.x;
    const float* xr = x + (size_t)row * Ddim;
    float* orow = o + (size_t)row * Ddim;
    int tid = threadIdx.x;          // 256 threads
    float v[4];
    float s = 0.f;
#pragma unroll
    for (int i = 0; i < 4; i++) { v[i] = xr[tid + i*256]; s += v[i]*v[i]; }
    __shared__ float red[8];
#pragma unroll
    for (int off = 16; off; off >>= 1) s += __shfl_xor_sync(0xffffffffu, s, off);
    if ((tid & 31) == 0) red[tid >> 5] = s;
    __syncthreads();
    float tot = 0.f;
#pragma unroll
    for (int i = 0; i < 8; i++) tot += red[i];
    float scale = rsqrtf(tot * (1.0f/Ddim) + EPSV);
#pragma unroll
    for (int i = 0; i < 4; i++) orow[tid + i*256] = w[tid + i*256] * (v[i] * scale);
}

// ---------------- SGEMM: C[M,N] = A[M,K] @ B[N,K]^T (+res) -------------------
// All M,N multiples of 128, K multiple of 8 (guaranteed by the shapes here).
__global__ void __launch_bounds__(256) gemm_nt(
    const float* __restrict__ A, const float* __restrict__ Bm,
    const float* __restrict__ res, float* __restrict__ C,
    int M, int N, int K) {
    __shared__ float As[8][128];
    __shared__ float Bs[8][128];
    int bm = blockIdx.y * 128, bn = blockIdx.x * 128;
    int tid = threadIdx.x;
    int tx = tid & 15, ty = tid >> 4;
    int lrow = tid >> 1;
    int lcol = (tid & 1) * 4;
    const float* Ap = A + (size_t)(bm + lrow) * K + lcol;
    const float* Bp = Bm + (size_t)(bn + lrow) * K + lcol;
    float acc[8][8] = {};
    for (int k0 = 0; k0 < K; k0 += 8) {
        float4 av = *reinterpret_cast<const float4*>(Ap + k0);
        float4 bv = *reinterpret_cast<const float4*>(Bp + k0);
        As[lcol+0][lrow] = av.x; As[lcol+1][lrow] = av.y;
        As[lcol+2][lrow] = av.z; As[lcol+3][lrow] = av.w;
        Bs[lcol+0][lrow] = bv.x; Bs[lcol+1][lrow] = bv.y;
        Bs[lcol+2][lrow] = bv.z; Bs[lcol+3][lrow] = bv.w;
        __syncthreads();
#pragma unroll
        for (int kk = 0; kk < 8; kk++) {
            float a[8], b[8];
            *(float4*)&a[0] = *(const float4*)&As[kk][ty*8];
            *(float4*)&a[4] = *(const float4*)&As[kk][ty*8+4];
            *(float4*)&b[0] = *(const float4*)&Bs[kk][tx*8];
            *(float4*)&b[4] = *(const float4*)&Bs[kk][tx*8+4];
#pragma unroll
            for (int i = 0; i < 8; i++)
#pragma unroll
                for (int j = 0; j < 8; j++)
                    acc[i][j] = fmaf(a[i], b[j], acc[i][j]);
        }
        __syncthreads();
    }
#pragma unroll
    for (int i = 0; i < 8; i++) {
        int r = bm + ty*8 + i;
#pragma unroll
        for (int j = 0; j < 8; j++) {
            int c = bn + tx*8 + j;
            float v = acc[i][j];
            if (res) v += res[(size_t)r * N + c];
            C[(size_t)r * N + c] = v;
        }
    }
}

// ---------------- attention scores + mask ------------------------------------
// mask_mode: 0 none, 1 local band, 2 dilated band
__global__ void attn_scores(const float* __restrict__ Q, const float* __restrict__ Kb,
                            float* __restrict__ S, int lq, int lk, int mask_mode,
                            const unsigned char* __restrict__ kpm) {
    int l = blockIdx.x;
    int bh = blockIdx.y;
    int b = bh / Hdim, h = bh % Hdim;
    __shared__ float qs[HDdim];
    int tid = threadIdx.x;  // 128
    if (tid < HDdim) qs[tid] = Q[((size_t)(b*lq + l))*Ddim + h*HDdim + tid];
    __syncthreads();
    int warp = tid >> 5, lane = tid & 31;
    float* srow = S + ((size_t)bh * lq + l) * lk;
    for (int m = warp; m < lk; m += 4) {
        const float* krow = Kb + ((size_t)(b*lk + m))*Ddim + h*HDdim;
        float p = qs[lane]*krow[lane] + qs[lane+32]*krow[lane+32];
#pragma unroll
        for (int off = 16; off; off >>= 1) p += __shfl_down_sync(0xffffffffu, p, off);
        if (lane == 0) {
            float s = p * 0.125f;  // 1/sqrt(64)
            int j = m - l;
            if (mask_mode == 1) {
                if (j > WINv || j < -WINv) s = -INFINITY;
            } else if (mask_mode == 2) {
                if (j > WINv || j < -WINv || (j % DILv) != 0) s = -INFINITY;
            }
            if (kpm != nullptr && kpm[b*lk + m]) s = -INFINITY;
            srow[m] = s;
        }
    }
}

// ---------------- row softmax ------------------------------------------------
__global__ void softmax_rows(float* __restrict__ S, int lk) {
    float* s = S + (size_t)blockIdx.x * lk;
    int tid = threadIdx.x;  // 256
    __shared__ float red[8];
    float m = -INFINITY;
    for (int i = tid; i < lk; i += 256) m = fmaxf(m, s[i]);
#pragma unroll
    for (int off = 16; off; off >>= 1) m = fmaxf(m, __shfl_xor_sync(0xffffffffu, m, off));
    if ((tid & 31) == 0) red[tid >> 5] = m;
    __syncthreads();
    float mm = -INFINITY;
#pragma unroll
    for (int i = 0; i < 8; i++) mm = fmaxf(mm, red[i]);
    __syncthreads();
    float sum = 0.f;
    for (int i = tid; i < lk; i += 256) {
        float e = expf(s[i] - mm);
        s[i] = e;
        sum += e;
    }
#pragma unroll
    for (int off = 16; off; off >>= 1) sum += __shfl_xor_sync(0xffffffffu, sum, off);
    if ((tid & 31) == 0) red[tid >> 5] = sum;
    __syncthreads();
    float tot = 0.f;
#pragma unroll
    for (int i = 0; i < 8; i++) tot += red[i];
    float inv = 1.0f / tot;
    for (int i = tid; i < lk; i += 256) s[i] *= inv;
}

// ---------------- O = P @ V --------------------------------------------------
__global__ void attn_av(const float* __restrict__ S, const float* __restrict__ Vb,
                        float* __restrict__ O, int lq, int lk) {
    int l = blockIdx.x;
    int bh = blockIdx.y;
    int b = bh / Hdim, h = bh % Hdim;
    int d = threadIdx.x;  // 64
    __shared__ float ps[64];
    const float* srow = S + ((size_t)bh * lq + l) * lk;
    float acc = 0.f;
    for (int m0 = 0; m0 < lk; m0 += 64) {
        __syncthreads();
        ps[d] = srow[m0 + d];
        __syncthreads();
#pragma unroll 8
        for (int mi = 0; mi < 64; mi++)
            acc += ps[mi] * Vb[((size_t)(b*lk + m0 + mi))*Ddim + h*HDdim + d];
    }
    O[((size_t)(b*lq + l))*Ddim + h*HDdim + d] = acc;
}

// ---------------- gated fusion -----------------------------------------------
__global__ void gate_fuse(const float* __restrict__ x, const float* __restrict__ h,
                          const float* __restrict__ o0, const float* __restrict__ o1,
                          const float* __restrict__ o2, const float* __restrict__ o3,
                          const float* __restrict__ gw, const float* __restrict__ gb,
                          float* __restrict__ out) {
    int row = blockIdx.x;  // B*L
    int tid = threadIdx.x; // 128
    int warp = tid >> 5, lane = tid & 31;
    __shared__ float wsh[4];
    const float* hr = h + (size_t)row * Ddim;
    float p = 0.f;
    const float* gwr = gw + warp * Ddim;
    for (int dd = lane; dd < Ddim; dd += 32) p += hr[dd] * gwr[dd];
#pragma unroll
    for (int off = 16; off; off >>= 1) p += __shfl_down_sync(0xffffffffu, p, off);
    if (lane == 0) wsh[warp] = p + gb[warp];
    __syncthreads();
    if (tid == 0) {
        float mx = fmaxf(fmaxf(wsh[0], wsh[1]), fmaxf(wsh[2], wsh[3]));
        float e0 = expf(wsh[0]-mx), e1 = expf(wsh[1]-mx), e2 = expf(wsh[2]-mx), e3 = expf(wsh[3]-mx);
        float inv = 1.0f / (e0+e1+e2+e3);
        wsh[0] = e0*inv; wsh[1] = e1*inv; wsh[2] = e2*inv; wsh[3] = e3*inv;
    }
    __syncthreads();
    float w0 = wsh[0], w1 = wsh[1], w2 = wsh[2], w3 = wsh[3];
    size_t base = (size_t)row * Ddim;
    for (int dd = tid; dd < Ddim; dd += 128)
        out[base+dd] = x[base+dd] + w0*o0[base+dd] + w1*o1[base+dd]
                                  + w2*o2[base+dd] + w3*o3[base+dd];
}

// ---------------- elementwise helpers ----------------------------------------
__global__ void broadcast_k(const float* __restrict__ src, float* __restrict__ dst,
                            int n, int total) {
    int i = blockIdx.x*256 + threadIdx.x;
    if (i < total) dst[i] = src[i % n];
}
__global__ void ema_k(const float* __restrict__ prev, const float* __restrict__ delta,
                      float* __restrict__ mem, int n) {
    int i = blockIdx.x*256 + threadIdx.x;
    if (i < n) mem[i] = 0.9f*prev[i] + 0.1f*(prev[i] + delta[i]);
}
__global__ void silu_mul_k(const float* __restrict__ u, float* __restrict__ o, int n) {
    int i = blockIdx.x*256 + threadIdx.x;
    if (i < n) {
        int r = i / DFFdim, f = i % DFFdim;
        float a = u[(size_t)r*2*DFFdim + f];
        float g = u[(size_t)r*2*DFFdim + DFFdim + f];
        o[i] = (a / (1.0f + expf(-a))) * g;
    }
}
__global__ void copy_k(const float* __restrict__ src, float* __restrict__ dst, int n) {
    int i = blockIdx.x*256 + threadIdx.x;
    if (i < n) dst[i] = src[i];
}

// ---------------- host-side MHA orchestration --------------------------------
static void run_mha(const float* qin, const float* kvin, const float* w,
                    int lq, int lk, int mask_mode, const unsigned char* kpm,
                    const float* res, float* out,
                    float* Qb, float* Kb, float* Vb, float* Ob, float* Sb) {
    const float* Wq = w;
    const float* Wk = w + Ddim*Ddim;
    const float* Wv = w + 2*Ddim*Ddim;
    const float* Wo = w + 3*Ddim*Ddim;
    int Mq = Bdim * lq, Mk = Bdim * lk;
    gemm_nt<<<dim3(Ddim/128, Mq/128), 256>>>(qin, Wq, nullptr, Qb, Mq, Ddim, Ddim);
    gemm_nt<<<dim3(Ddim/128, Mk/128), 256>>>(kvin, Wk, nullptr, Kb, Mk, Ddim, Ddim);
    gemm_nt<<<dim3(Ddim/128, Mk/128), 256>>>(kvin, Wv, nullptr, Vb, Mk, Ddim, Ddim);
    attn_scores<<<dim3(lq, Bdim*Hdim), 128>>>(Qb, Kb, Sb, lq, lk, mask_mode, kpm);
    softmax_rows<<<Bdim*Hdim*lq, 256>>>(Sb, lk);
    attn_av<<<dim3(lq, Bdim*Hdim), 64>>>(Sb, Vb, Ob, lq, lk);
    gemm_nt<<<dim3(Ddim/128, Mq/128), 256>>>(Ob, Wo, res, out, Mq, Ddim, Ddim);
}

#define SYMF(name) ({ void* _p = nullptr; cudaGetSymbolAddress(&_p, name); (float*)_p; })

extern "C" void kernel_launch(void* const* d_in, const int* in_sizes, int n_in,
                              void* d_out, int out_size) {
    const float* x          = (const float*)d_in[0];
    const unsigned char* kpm = (const unsigned char*)d_in[1];
    const float* norm_w     = (const float*)d_in[2];
    const float* ld_nq      = (const float*)d_in[3];
    const float* ld_nk      = (const float*)d_in[4];
    const float* local_w    = (const float*)d_in[5];
    const float* dil_w      = (const float*)d_in[6];
    const float* lat_tokens = (const float*)d_in[7];
    const float* lp_nq      = (const float*)d_in[8];
    const float* lp_nk      = (const float*)d_in[9];
    const float* lat_to_w   = (const float*)d_in[10];
    const float* lat_from_w = (const float*)d_in[11];
    const float* mem_tokens = (const float*)d_in[12];
    const float* mem_nq     = (const float*)d_in[13];
    const float* mem_nk     = (const float*)d_in[14];
    const float* mem_read_w = (const float*)d_in[15];
    const float* mem_write_w= (const float*)d_in[16];
    const float* gate_w     = (const float*)d_in[17];
    const float* gate_b     = (const float*)d_in[18];
    const float* up_w       = (const float*)d_in[19];
    const float* down_w     = (const float*)d_in[20];
    float* out = (float*)d_out;

    float* hB   = SYMF(g_h);
    float* qnB  = SYMF(g_qn);
    float* knB  = SYMF(g_kn);
    float* QB   = SYMF(g_Q);
    float* KB   = SYMF(g_K);
    float* VB   = SYMF(g_V);
    float* OB   = SYMF(g_O);
    float* oLB  = SYMF(g_oL);
    float* oDB  = SYMF(g_oD);
    float* xlatB= SYMF(g_xlat);
    float* xmemB= SYMF(g_xmem);
    float* x1B  = SYMF(g_x1);
    float* hnB  = SYMF(g_hn);
    float* SB   = SYMF(g_S);
    float* latprevB = SYMF(g_latprev);
    float* latB  = SYMF(g_lat);
    float* latqB = SYMF(g_latq);
    float* latkB = SYMF(g_latk);
    float* memprevB = SYMF(g_memprev);
    float* memB  = SYMF(g_mem);
    float* memqB = SYMF(g_memq);
    float* memkB = SYMF(g_memk);
    float* memdB = SYMF(g_memdelta);
    float* uB    = SYMF(g_u);
    float* gactB = SYMF(g_gact);

    const int rowsBL = Bdim * Ldim;

    // h = rmsnorm(x, norm_w)
    rmsnorm_k<<<rowsBL, 256>>>(x, norm_w, hB);

    // local + dilated branches (shared q/k norms)
    rmsnorm_k<<<rowsBL, 256>>>(hB, ld_nq, qnB);
    rmsnorm_k<<<rowsBL, 256>>>(hB, ld_nk, knB);
    run_mha(qnB, knB, local_w, Ldim, Ldim, 1, kpm, nullptr, oLB, QB, KB, VB, OB, SB);
    run_mha(qnB, knB, dil_w,   Ldim, Ldim, 2, kpm, nullptr, oDB, QB, KB, VB, OB, SB);

    // latent pool
    broadcast_k<<<(BKD+255)/256, 256>>>(lat_tokens, latprevB, KLAT*Ddim, BKD);
    rmsnorm_k<<<Bdim*KLAT, 256>>>(latprevB, lp_nq, latqB);
    rmsnorm_k<<<rowsBL, 256>>>(hB, lp_nk, knB);
    run_mha(latqB, knB, lat_to_w, KLAT, Ldim, 0, kpm, latprevB, latB, QB, KB, VB, OB, SB);
    rmsnorm_k<<<rowsBL, 256>>>(hB, lp_nq, qnB);
    rmsnorm_k<<<Bdim*KLAT, 256>>>(latB, lp_nk, latkB);
    run_mha(qnB, latkB, lat_from_w, Ldim, KLAT, 0, nullptr, hB, xlatB, QB, KB, VB, OB, SB);

    // infini-memory
    broadcast_k<<<(BMD+255)/256, 256>>>(mem_tokens, memprevB, MMEM*Ddim, BMD);
    rmsnorm_k<<<Bdim*MMEM, 256>>>(memprevB, mem_nq, memqB);
    rmsnorm_k<<<rowsBL, 256>>>(hB, mem_nk, knB);
    run_mha(memqB, knB, mem_write_w, MMEM, Ldim, 0, kpm, nullptr, memdB, QB, KB, VB, OB, SB);
    ema_k<<<(BMD+255)/256, 256>>>(memprevB, memdB, memB, BMD);
    rmsnorm_k<<<rowsBL, 256>>>(hB, mem_nq, qnB);
    rmsnorm_k<<<Bdim*MMEM, 256>>>(memB, mem_nk, memkB);
    run_mha(qnB, memkB, mem_read_w, Ldim, MMEM, 0, nullptr, hB, xmemB, QB, KB, VB, OB, SB);

    // gated fusion
    gate_fuse<<<rowsBL, 128>>>(x, hB, oLB, oDB, xlatB, xmemB, gate_w, gate_b, x1B);

    // SwiGLU FFN (pre-norm with norm_w), residual into d_out
    rmsnorm_k<<<rowsBL, 256>>>(x1B, norm_w, hnB);
    gemm_nt<<<dim3(2*DFFdim/128, rowsBL/128), 256>>>(hnB, up_w, nullptr, uB, rowsBL, 2*DFFdim, Ddim);
    int nact = rowsBL * DFFdim;
    silu_mul_k<<<(nact+255)/256, 256>>>(uB, gactB, nact);
    gemm_nt<<<dim3(Ddim/128, rowsBL/128), 256>>>(gactB, down_w, x1B, out, rowsBL, Ddim, DFFdim);

    // lat + mem outputs
    copy_k<<<(BKD+255)/256, 256>>>(latB, out + (size_t)BLD, BKD);
    copy_k<<<(BMD+255)/256, 256>>>(memB, out + (size_t)BLD + BKD, BMD);
}

// round 2
// speedup vs baseline: 4.4828x; 4.4828x over previous
#include <cuda_runtime.h>
#include <math.h>
#include <stdint.h>

#define Bdim 2
#define Ldim 1024
#define Ddim 1024
#define Hdim 16
#define HDdim 64
#define DFFdim 4096
#define WINv 128
#define DILv 4
#define KLAT 64
#define MMEM 64
#define EPSV 1e-6f

#define BLD (Bdim*Ldim*Ddim)
#define BKD (Bdim*KLAT*Ddim)
#define BMD (Bdim*MMEM*Ddim)

// ---------------- scratch (static device memory; no allocations) -------------
__device__ float g_h[BLD];
__device__ float g_qn[BLD];
__device__ float g_kn[BLD];
__device__ float g_Q[BLD];
__device__ float g_K[BLD];
__device__ float g_V[BLD];
__device__ float g_O[BLD];
__device__ float g_oL[BLD];
__device__ float g_oD[BLD];
__device__ float g_xlat[BLD];
__device__ float g_xmem[BLD];
__device__ float g_x1[BLD];
__device__ float g_hn[BLD];
__device__ float g_latprev[BKD];
__device__ float g_lat[BKD];
__device__ float g_latq[BKD];
__device__ float g_latk[BKD];
__device__ float g_memprev[BMD];
__device__ float g_mem[BMD];
__device__ float g_memq[BMD];
__device__ float g_memk[BMD];
__device__ float g_memdelta[BMD];
__device__ float g_u[(size_t)Bdim*Ldim*2*DFFdim];      // 64 MB
__device__ float g_gact[(size_t)Bdim*Ldim*DFFdim];     // 32 MB

// ---------------- rmsnorm: one block per row, D=1024 -------------------------
__global__ void rmsnorm_k(const float* __restrict__ x, const float* __restrict__ w,
                          float* __restrict__ o) {
    int row = blockIdx.x;
    const float* xr = x + (size_t)row * Ddim;
    float* orow = o + (size_t)row * Ddim;
    int tid = threadIdx.x;          // 256 threads
    float v[4];
    float s = 0.f;
#pragma unroll
    for (int i = 0; i < 4; i++) { v[i] = xr[tid + i*256]; s += v[i]*v[i]; }
    __shared__ float red[8];
#pragma unroll
    for (int off = 16; off; off >>= 1) s += __shfl_xor_sync(0xffffffffu, s, off);
    if ((tid & 31) == 0) red[tid >> 5] = s;
    __syncthreads();
    float tot = 0.f;
#pragma unroll
    for (int i = 0; i < 8; i++) tot += red[i];
    float scale = rsqrtf(tot * (1.0f/Ddim) + EPSV);
#pragma unroll
    for (int i = 0; i < 4; i++) orow[tid + i*256] = w[tid + i*256] * (v[i] * scale);
}

// ---------------- tf32 tensor-core GEMM: C[M,N] = A[M,K] @ B[N,K]^T (+res) ---
// M,N multiples of 128; K multiple of 16. A,B row-major with K contiguous.
__device__ __forceinline__ uint32_t f2tf(float f) {
    uint32_t u;
    asm("cvt.rna.tf32.f32 %0, %1;" : "=r"(u) : "f"(f));
    return u;
}
__device__ __forceinline__ void mma_tf32(float* c, const uint32_t* a, const uint32_t* b) {
    asm volatile("mma.sync.aligned.m16n8k8.row.col.f32.tf32.tf32.f32 "
        "{%0,%1,%2,%3}, {%4,%5,%6,%7}, {%8,%9}, {%0,%1,%2,%3};"
        : "+f"(c[0]), "+f"(c[1]), "+f"(c[2]), "+f"(c[3])
        : "r"(a[0]), "r"(a[1]), "r"(a[2]), "r"(a[3]), "r"(b[0]), "r"(b[1]));
}

__global__ void __launch_bounds__(128) gemm_tf32(
    const float* __restrict__ A, const float* __restrict__ Bm,
    const float* __restrict__ res, float* __restrict__ C,
    int M, int N, int K) {
    __shared__ uint32_t As[2][128][20];   // stride 20 -> conflict-free frag loads
    __shared__ uint32_t Bs[2][128][20];
    int tid = threadIdx.x, lane = tid & 31, wid = tid >> 5;
    int bm = blockIdx.y * 128, bn = blockIdx.x * 128;
    int wm = (wid & 1) * 64, wn = (wid >> 1) * 64;

    int lrow = tid >> 2;          // 0..31 (+ i*32)
    int lkq  = (tid & 3) * 4;     // k offset within tile
    const float* Ag = A + (size_t)(bm + lrow) * K + lkq;
    const float* Bg = Bm + (size_t)(bn + lrow) * K + lkq;

    float c[4][8][4] = {};
    int ntiles = K >> 4;

    float4 la[4], lb[4];
    // prologue: tile 0
#pragma unroll
    for (int i = 0; i < 4; i++) {
        la[i] = *reinterpret_cast<const float4*>(Ag + (size_t)i*32*K);
        lb[i] = *reinterpret_cast<const float4*>(Bg + (size_t)i*32*K);
    }
#pragma unroll
    for (int i = 0; i < 4; i++) {
        int m = lrow + i*32;
        As[0][m][lkq+0] = f2tf(la[i].x); As[0][m][lkq+1] = f2tf(la[i].y);
        As[0][m][lkq+2] = f2tf(la[i].z); As[0][m][lkq+3] = f2tf(la[i].w);
        Bs[0][m][lkq+0] = f2tf(lb[i].x); Bs[0][m][lkq+1] = f2tf(lb[i].y);
        Bs[0][m][lkq+2] = f2tf(lb[i].z); Bs[0][m][lkq+3] = f2tf(lb[i].w);
    }
    __syncthreads();

    for (int kt = 0; kt < ntiles; kt++) {
        int cur = kt & 1;
        if (kt + 1 < ntiles) {
            const float* Ap = Ag + (size_t)(kt+1)*16;
            const float* Bp = Bg + (size_t)(kt+1)*16;
#pragma unroll
            for (int i = 0; i < 4; i++) {
                la[i] = *reinterpret_cast<const float4*>(Ap + (size_t)i*32*K);
                lb[i] = *reinterpret_cast<const float4*>(Bp + (size_t)i*32*K);
            }
        }
#pragma unroll
        for (int ks = 0; ks < 2; ks++) {
            int kb = ks*8 + (lane & 3);
            int rA = wm + (lane >> 2);
            int rB = wn + (lane >> 2);
            uint32_t a[4][4], b[8][2];
#pragma unroll
            for (int mt = 0; mt < 4; mt++) {
                a[mt][0] = As[cur][rA + mt*16    ][kb];
                a[mt][1] = As[cur][rA + mt*16 + 8][kb];
                a[mt][2] = As[cur][rA + mt*16    ][kb+4];
                a[mt][3] = As[cur][rA + mt*16 + 8][kb+4];
            }
#pragma unroll
            for (int nt = 0; nt < 8; nt++) {
                b[nt][0] = Bs[cur][rB + nt*8][kb];
                b[nt][1] = Bs[cur][rB + nt*8][kb+4];
            }
#pragma unroll
            for (int mt = 0; mt < 4; mt++)
#pragma unroll
                for (int nt = 0; nt < 8; nt++)
                    mma_tf32(c[mt][nt], a[mt], b[nt]);
        }
        if (kt + 1 < ntiles) {
            int nxt = cur ^ 1;
#pragma unroll
            for (int i = 0; i < 4; i++) {
                int m = lrow + i*32;
                As[nxt][m][lkq+0] = f2tf(la[i].x); As[nxt][m][lkq+1] = f2tf(la[i].y);
                As[nxt][m][lkq+2] = f2tf(la[i].z); As[nxt][m][lkq+3] = f2tf(la[i].w);
                Bs[nxt][m][lkq+0] = f2tf(lb[i].x); Bs[nxt][m][lkq+1] = f2tf(lb[i].y);
                Bs[nxt][m][lkq+2] = f2tf(lb[i].z); Bs[nxt][m][lkq+3] = f2tf(lb[i].w);
            }
        }
        __syncthreads();
    }

    // epilogue
#pragma unroll
    for (int mt = 0; mt < 4; mt++) {
        int r0 = bm + wm + mt*16 + (lane >> 2);
#pragma unroll
        for (int nt = 0; nt < 8; nt++) {
            int cc = bn + wn + nt*8 + (lane & 3)*2;
            float2 v0 = make_float2(c[mt][nt][0], c[mt][nt][1]);
            float2 v1 = make_float2(c[mt][nt][2], c[mt][nt][3]);
            if (res) {
                float2 q0 = *reinterpret_cast<const float2*>(&res[(size_t)r0*N + cc]);
                float2 q1 = *reinterpret_cast<const float2*>(&res[(size_t)(r0+8)*N + cc]);
                v0.x += q0.x; v0.y += q0.y; v1.x += q1.x; v1.y += q1.y;
            }
            *reinterpret_cast<float2*>(&C[(size_t)r0*N + cc]) = v0;
            *reinterpret_cast<float2*>(&C[(size_t)(r0+8)*N + cc]) = v1;
        }
    }
}

// ---------------- fused flash attention (per (b,h), 64-query tiles) ----------
// mask_mode: 0 none, 1 local band, 2 dilated band
#define ATTN_SMEM (4*64*68*4 + 3*64*4)
__global__ void __launch_bounds__(256) fattn(
    const float* __restrict__ Q, const float* __restrict__ Kg,
    const float* __restrict__ Vg, float* __restrict__ O,
    int lq, int lk, int mask_mode, const unsigned char* __restrict__ kpm) {
    extern __shared__ float sm[];
    float (*Qs)[68] = (float(*)[68])sm;
    float (*Ks)[68] = (float(*)[68])(sm + 64*68);
    float (*Vs)[68] = (float(*)[68])(sm + 2*64*68);
    float (*Ps)[68] = (float(*)[68])(sm + 3*64*68);
    float* m_s  = sm + 4*64*68;
    float* l_s  = m_s + 64;
    float* al_s = l_s + 64;

    int tid = threadIdx.x;
    int q0 = blockIdx.x * 64;
    int bh = blockIdx.y;
    int b = bh >> 4, h = bh & 15;

    // load Q tile (64x64)
#pragma unroll
    for (int i = 0; i < 4; i++) {
        int id = tid + i*256;
        int r = id >> 4, dq = (id & 15) * 4;
        *reinterpret_cast<float4*>(&Qs[r][dq]) =
            *reinterpret_cast<const float4*>(&Q[((size_t)(b*lq + q0 + r))*Ddim + h*HDdim + dq]);
    }
    if (tid < 64) { m_s[tid] = -INFINITY; l_s[tid] = 0.f; }
    __syncthreads();

    int ty = tid >> 4, tx = tid & 15;
    int r0 = ty * 4;
    float o[4][4] = {};

    int c_lo = 0, c_hi = lk >> 6;
    if (mask_mode) {
        c_lo = (q0 >= WINv) ? (q0 - WINv) >> 6 : 0;
        int hi = (q0 + 64 + WINv) >> 6;
        if (hi < c_hi) c_hi = hi;
    }

    for (int ck = c_lo; ck < c_hi; ck++) {
        int kb = ck * 64;
#pragma unroll
        for (int i = 0; i < 4; i++) {
            int id = tid + i*256;
            int r = id >> 4, dq = (id & 15)*4;
            size_t g = ((size_t)(b*lk + kb + r))*Ddim + h*HDdim + dq;
            *reinterpret_cast<float4*>(&Ks[r][dq]) = *reinterpret_cast<const float4*>(&Kg[g]);
            *reinterpret_cast<float4*>(&Vs[r][dq]) = *reinterpret_cast<const float4*>(&Vg[g]);
        }
        __syncthreads();

        // S tile: thread covers rows r0..r0+3, cols {tx, tx+16, tx+32, tx+48}
        float s[4][4] = {};
#pragma unroll
        for (int k = 0; k < 64; k += 4) {
            float4 qv[4], kv[4];
#pragma unroll
            for (int i = 0; i < 4; i++) qv[i] = *reinterpret_cast<float4*>(&Qs[r0+i][k]);
#pragma unroll
            for (int j = 0; j < 4; j++) kv[j] = *reinterpret_cast<float4*>(&Ks[tx + 16*j][k]);
#pragma unroll
            for (int i = 0; i < 4; i++)
#pragma unroll
                for (int j = 0; j < 4; j++)
                    s[i][j] += qv[i].x*kv[j].x + qv[i].y*kv[j].y
                             + qv[i].z*kv[j].z + qv[i].w*kv[j].w;
        }
        // mask + write P (pre-softmax scores)
#pragma unroll
        for (int i = 0; i < 4; i++) {
            int qr = q0 + r0 + i;
#pragma unroll
            for (int j = 0; j < 4; j++) {
                int col = kb + tx + 16*j;
                float v = s[i][j] * 0.125f;
                int jr = col - qr;
                bool ok = true;
                if (mask_mode == 1) ok = (jr <= WINv && jr >= -WINv);
                else if (mask_mode == 2) ok = (jr <= WINv && jr >= -WINv && ((jr & 3) == 0));
                if (kpm && kpm[b*lk + col]) ok = false;
                Ps[r0+i][tx + 16*j] = ok ? v : -INFINITY;
            }
        }
        __syncthreads();

        // online softmax: warp w handles rows w*8 .. w*8+7
        {
            int w = tid >> 5, ln = tid & 31;
            for (int rr = w*8; rr < w*8 + 8; rr++) {
                float s0 = Ps[rr][ln], s1 = Ps[rr][ln+32];
                float mx = fmaxf(s0, s1);
#pragma unroll
                for (int off = 16; off; off >>= 1)
                    mx = fmaxf(mx, __shfl_xor_sync(0xffffffffu, mx, off));
                float mo = m_s[rr];
                float mn = fmaxf(mo, mx);
                float p0, p1, alpha;
                if (mn == -INFINITY) { p0 = 0.f; p1 = 0.f; alpha = 1.f; }
                else {
                    alpha = __expf(mo - mn);
                    p0 = (s0 == -INFINITY) ? 0.f : __expf(s0 - mn);
                    p1 = (s1 == -INFINITY) ? 0.f : __expf(s1 - mn);
                }
                Ps[rr][ln] = p0; Ps[rr][ln+32] = p1;
                float sum = p0 + p1;
#pragma unroll
                for (int off = 16; off; off >>= 1)
                    sum += __shfl_xor_sync(0xffffffffu, sum, off);
                if (ln == 0) {
                    l_s[rr] = l_s[rr]*alpha + sum;
                    m_s[rr] = mn;
                    al_s[rr] = alpha;
                }
            }
        }
        __syncthreads();

        // O accumulate: dims tx*4 .. tx*4+3
#pragma unroll
        for (int i = 0; i < 4; i++) {
            float a = al_s[r0+i];
#pragma unroll
            for (int j = 0; j < 4; j++) o[i][j] *= a;
        }
#pragma unroll
        for (int k = 0; k < 64; k += 4) {
            float4 pk[4];
#pragma unroll
            for (int i = 0; i < 4; i++) pk[i] = *reinterpret_cast<float4*>(&Ps[r0+i][k]);
#pragma unroll
            for (int kk = 0; kk < 4; kk++) {
                float4 vv = *reinterpret_cast<float4*>(&Vs[k+kk][tx*4]);
#pragma unroll
                for (int i = 0; i < 4; i++) {
                    float p = (kk == 0) ? pk[i].x : (kk == 1) ? pk[i].y : (kk == 2) ? pk[i].z : pk[i].w;
                    o[i][0] += p*vv.x; o[i][1] += p*vv.y; o[i][2] += p*vv.z; o[i][3] += p*vv.w;
                }
            }
        }
        __syncthreads();
    }

    // finalize
#pragma unroll
    for (int i = 0; i < 4; i++) {
        float inv = 1.0f / l_s[r0+i];
        float4 ov = make_float4(o[i][0]*inv, o[i][1]*inv, o[i][2]*inv, o[i][3]*inv);
        *reinterpret_cast<float4*>(&O[((size_t)(b*lq + q0 + r0 + i))*Ddim + h*HDdim + tx*4]) = ov;
    }
}

// ---------------- gated fusion -----------------------------------------------
__global__ void gate_fuse(const float* __restrict__ x, const float* __restrict__ h,
                          const float* __restrict__ o0, const float* __restrict__ o1,
                          const float* __restrict__ o2, const float* __restrict__ o3,
                          const float* __restrict__ gw, const float* __restrict__ gb,
                          float* __restrict__ out) {
    int row = blockIdx.x;  // B*L
    int tid = threadIdx.x; // 128
    int warp = tid >> 5, lane = tid & 31;
    __shared__ float wsh[4];
    const float* hr = h + (size_t)row * Ddim;
    float p = 0.f;
    const float* gwr = gw + warp * Ddim;
    for (int dd = lane; dd < Ddim; dd += 32) p += hr[dd] * gwr[dd];
#pragma unroll
    for (int off = 16; off; off >>= 1) p += __shfl_down_sync(0xffffffffu, p, off);
    if (lane == 0) wsh[warp] = p + gb[warp];
    __syncthreads();
    if (tid == 0) {
        float mx = fmaxf(fmaxf(wsh[0], wsh[1]), fmaxf(wsh[2], wsh[3]));
        float e0 = expf(wsh[0]-mx), e1 = expf(wsh[1]-mx), e2 = expf(wsh[2]-mx), e3 = expf(wsh[3]-mx);
        float inv = 1.0f / (e0+e1+e2+e3);
        wsh[0] = e0*inv; wsh[1] = e1*inv; wsh[2] = e2*inv; wsh[3] = e3*inv;
    }
    __syncthreads();
    float w0 = wsh[0], w1 = wsh[1], w2 = wsh[2], w3 = wsh[3];
    size_t base = (size_t)row * Ddim;
    for (int dd = tid; dd < Ddim; dd += 128)
        out[base+dd] = x[base+dd] + w0*o0[base+dd] + w1*o1[base+dd]
                                  + w2*o2[base+dd] + w3*o3[base+dd];
}

// ---------------- elementwise helpers ----------------------------------------
__global__ void broadcast_k(const float* __restrict__ src, float* __restrict__ dst,
                            int n, int total) {
    int i = blockIdx.x*256 + threadIdx.x;
    if (i < total) dst[i] = src[i % n];
}
__global__ void ema_k(const float* __restrict__ prev, const float* __restrict__ delta,
                      float* __restrict__ mem, int n) {
    int i = blockIdx.x*256 + threadIdx.x;
    if (i < n) mem[i] = 0.9f*prev[i] + 0.1f*(prev[i] + delta[i]);
}
__global__ void silu_mul_k(const float* __restrict__ u, float* __restrict__ o, int n) {
    int i = blockIdx.x*256 + threadIdx.x;
    if (i < n) {
        int r = i / DFFdim, f = i % DFFdim;
        float a = u[(size_t)r*2*DFFdim + f];
        float g = u[(size_t)r*2*DFFdim + DFFdim + f];
        o[i] = (a / (1.0f + expf(-a))) * g;
    }
}
__global__ void copy_k(const float* __restrict__ src, float* __restrict__ dst, int n) {
    int i = blockIdx.x*256 + threadIdx.x;
    if (i < n) dst[i] = src[i];
}

// ---------------- host-side MHA orchestration --------------------------------
static void run_mha(const float* qin, const float* kvin, const float* w,
                    int lq, int lk, int mask_mode, const unsigned char* kpm,
                    const float* res, float* out,
                    float* Qb, float* Kb, float* Vb, float* Ob) {
    const float* Wq = w;
    const float* Wk = w + Ddim*Ddim;
    const float* Wv = w + 2*Ddim*Ddim;
    const float* Wo = w + 3*Ddim*Ddim;
    int Mq = Bdim * lq, Mk = Bdim * lk;
    gemm_tf32<<<dim3(Ddim/128, Mq/128), 128>>>(qin, Wq, nullptr, Qb, Mq, Ddim, Ddim);
    gemm_tf32<<<dim3(Ddim/128, Mk/128), 128>>>(kvin, Wk, nullptr, Kb, Mk, Ddim, Ddim);
    gemm_tf32<<<dim3(Ddim/128, Mk/128), 128>>>(kvin, Wv, nullptr, Vb, Mk, Ddim, Ddim);
    fattn<<<dim3(lq/64, Bdim*Hdim), 256, ATTN_SMEM>>>(Qb, Kb, Vb, Ob, lq, lk, mask_mode, kpm);
    gemm_tf32<<<dim3(Ddim/128, Mq/128), 128>>>(Ob, Wo, res, out, Mq, Ddim, Ddim);
}

#define SYMF(name) ({ void* _p = nullptr; cudaGetSymbolAddress(&_p, name); (float*)_p; })

extern "C" void kernel_launch(void* const* d_in, const int* in_sizes, int n_in,
                              void* d_out, int out_size) {
    const float* x          = (const float*)d_in[0];
    const unsigned char* kpm = (const unsigned char*)d_in[1];
    const float* norm_w     = (const float*)d_in[2];
    const float* ld_nq      = (const float*)d_in[3];
    const float* ld_nk      = (const float*)d_in[4];
    const float* local_w    = (const float*)d_in[5];
    const float* dil_w      = (const float*)d_in[6];
    const float* lat_tokens = (const float*)d_in[7];
    const float* lp_nq      = (const float*)d_in[8];
    const float* lp_nk      = (const float*)d_in[9];
    const float* lat_to_w   = (const float*)d_in[10];
    const float* lat_from_w = (const float*)d_in[11];
    const float* mem_tokens = (const float*)d_in[12];
    const float* mem_nq     = (const float*)d_in[13];
    const float* mem_nk     = (const float*)d_in[14];
    const float* mem_read_w = (const float*)d_in[15];
    const float* mem_write_w= (const float*)d_in[16];
    const float* gate_w     = (const float*)d_in[17];
    const float* gate_b     = (const float*)d_in[18];
    const float* up_w       = (const float*)d_in[19];
    const float* down_w     = (const float*)d_in[20];
    float* out = (float*)d_out;

    cudaFuncSetAttribute(fattn, cudaFuncAttributeMaxDynamicSharedMemorySize, ATTN_SMEM);

    float* hB   = SYMF(g_h);
    float* qnB  = SYMF(g_qn);
    float* knB  = SYMF(g_kn);
    float* QB   = SYMF(g_Q);
    float* KB   = SYMF(g_K);
    float* VB   = SYMF(g_V);
    float* OB   = SYMF(g_O);
    float* oLB  = SYMF(g_oL);
    float* oDB  = SYMF(g_oD);
    float* xlatB= SYMF(g_xlat);
    float* xmemB= SYMF(g_xmem);
    float* x1B  = SYMF(g_x1);
    float* hnB  = SYMF(g_hn);
    float* latprevB = SYMF(g_latprev);
    float* latB  = SYMF(g_lat);
    float* latqB = SYMF(g_latq);
    float* latkB = SYMF(g_latk);
    float* memprevB = SYMF(g_memprev);
    float* memB  = SYMF(g_mem);
    float* memqB = SYMF(g_memq);
    float* memkB = SYMF(g_memk);
    float* memdB = SYMF(g_memdelta);
    float* uB    = SYMF(g_u);
    float* gactB = SYMF(g_gact);

    const int rowsBL = Bdim * Ldim;

    // h = rmsnorm(x, norm_w)
    rmsnorm_k<<<rowsBL, 256>>>(x, norm_w, hB);

    // local + dilated branches (shared q/k norms)
    rmsnorm_k<<<rowsBL, 256>>>(hB, ld_nq, qnB);
    rmsnorm_k<<<rowsBL, 256>>>(hB, ld_nk, knB);
    run_mha(qnB, knB, local_w, Ldim, Ldim, 1, kpm, nullptr, oLB, QB, KB, VB, OB);
    run_mha(qnB, knB, dil_w,   Ldim, Ldim, 2, kpm, nullptr, oDB, QB, KB, VB, OB);

    // latent pool
    broadcast_k<<<(BKD+255)/256, 256>>>(lat_tokens, latprevB, KLAT*Ddim, BKD);
    rmsnorm_k<<<Bdim*KLAT, 256>>>(latprevB, lp_nq, latqB);
    rmsnorm_k<<<rowsBL, 256>>>(hB, lp_nk, knB);
    run_mha(latqB, knB, lat_to_w, KLAT, Ldim, 0, kpm, latprevB, latB, QB, KB, VB, OB);
    rmsnorm_k<<<rowsBL, 256>>>(hB, lp_nq, qnB);
    rmsnorm_k<<<Bdim*KLAT, 256>>>(latB, lp_nk, latkB);
    run_mha(qnB, latkB, lat_from_w, Ldim, KLAT, 0, nullptr, hB, xlatB, QB, KB, VB, OB);

    // infini-memory
    broadcast_k<<<(BMD+255)/256, 256>>>(mem_tokens, memprevB, MMEM*Ddim, BMD);
    rmsnorm_k<<<Bdim*MMEM, 256>>>(memprevB, mem_nq, memqB);
    rmsnorm_k<<<rowsBL, 256>>>(hB, mem_nk, knB);
    run_mha(memqB, knB, mem_write_w, MMEM, Ldim, 0, kpm, nullptr, memdB, QB, KB, VB, OB);
    ema_k<<<(BMD+255)/256, 256>>>(memprevB, memdB, memB, BMD);
    rmsnorm_k<<<rowsBL, 256>>>(hB, mem_nq, qnB);
    rmsnorm_k<<<Bdim*MMEM, 256>>>(memB, mem_nk, memkB);
    run_mha(qnB, memkB, mem_read_w, Ldim, MMEM, 0, nullptr, hB, xmemB, QB, KB, VB, OB);

    // gated fusion
    gate_fuse<<<rowsBL, 128>>>(x, hB, oLB, oDB, xlatB, xmemB, gate_w, gate_b, x1B);

    // SwiGLU FFN (pre-norm with norm_w), residual into d_out
    rmsnorm_k<<<rowsBL, 256>>>(x1B, norm_w, hnB);
    gemm_tf32<<<dim3(2*DFFdim/128, rowsBL/128), 128>>>(hnB, up_w, nullptr, uB, rowsBL, 2*DFFdim, Ddim);
    int nact = rowsBL * DFFdim;
    silu_mul_k<<<(nact+255)/256, 256>>>(uB, gactB, nact);
    gemm_tf32<<<dim3(Ddim/128, rowsBL/128), 128>>>(gactB, down_w, x1B, out, rowsBL, Ddim, DFFdim);

    // lat + mem outputs
    copy_k<<<(BKD+255)/256, 256>>>(latB, out + (size_t)BLD, BKD);
    copy_k<<<(BMD+255)/256, 256>>>(memB, out + (size_t)BLD + BKD, BMD);
}

// round 3
// speedup vs baseline: 5.0736x; 1.1318x over previous
#include <cuda_runtime.h>
#include <math.h>
#include <stdint.h>

#define Bdim 2
#define Ldim 1024
#define Ddim 1024
#define Hdim 16
#define HDdim 64
#define DFFdim 4096
#define WINv 128
#define DILv 4
#define KLAT 64
#define MMEM 64
#define EPSV 1e-6f

#define BLD (Bdim*Ldim*Ddim)
#define BKD (Bdim*KLAT*Ddim)
#define BMD (Bdim*MMEM*Ddim)

// ---------------- scratch (static device memory; no allocations) -------------
__device__ float g_h[BLD];
__device__ float g_qn[BLD];
__device__ float g_kn[BLD];
__device__ float g_Q[BLD];
__device__ float g_KV[(size_t)Bdim*Ldim*2*Ddim];       // fused K||V, 16 MB
__device__ float g_O[BLD];
__device__ float g_oL[BLD];
__device__ float g_oD[BLD];
__device__ float g_xlat[BLD];
__device__ float g_xmem[BLD];
__device__ float g_x1[BLD];
__device__ float g_hn[BLD];
__device__ float g_latprev[BKD];
__device__ float g_lat[BKD];
__device__ float g_latq[BKD];
__device__ float g_latk[BKD];
__device__ float g_memprev[BMD];
__device__ float g_mem[BMD];
__device__ float g_memq[BMD];
__device__ float g_memk[BMD];
__device__ float g_memdelta[BMD];
__device__ float g_u[(size_t)Bdim*Ldim*2*DFFdim];      // 64 MB
__device__ float g_gact[(size_t)Bdim*Ldim*DFFdim];     // 32 MB
__device__ float g_part[(size_t)2048*1024*2];          // split-K partials, 16 MB

// ---------------- rmsnorm ----------------------------------------------------
__global__ void rmsnorm_k(const float* __restrict__ x, const float* __restrict__ w,
                          float* __restrict__ o) {
    int row = blockIdx.x;
    const float* xr = x + (size_t)row * Ddim;
    float* orow = o + (size_t)row * Ddim;
    int tid = threadIdx.x;          // 256 threads
    float v[4];
    float s = 0.f;
#pragma unroll
    for (int i = 0; i < 4; i++) { v[i] = xr[tid + i*256]; s += v[i]*v[i]; }
    __shared__ float red[8];
#pragma unroll
    for (int off = 16; off; off >>= 1) s += __shfl_xor_sync(0xffffffffu, s, off);
    if ((tid & 31) == 0) red[tid >> 5] = s;
    __syncthreads();
    float tot = 0.f;
#pragma unroll
    for (int i = 0; i < 8; i++) tot += red[i];
    float scale = rsqrtf(tot * (1.0f/Ddim) + EPSV);
#pragma unroll
    for (int i = 0; i < 4; i++) orow[tid + i*256] = w[tid + i*256] * (v[i] * scale);
}

// ---------------- tf32 mma helpers -------------------------------------------
__device__ __forceinline__ uint32_t f2tf(float f) {
    uint32_t u;
    asm("cvt.rna.tf32.f32 %0, %1;" : "=r"(u) : "f"(f));
    return u;
}
__device__ __forceinline__ void mma_tf32(float* c, const uint32_t* a, const uint32_t* b) {
    asm volatile("mma.sync.aligned.m16n8k8.row.col.f32.tf32.tf32.f32 "
        "{%0,%1,%2,%3}, {%4,%5,%6,%7}, {%8,%9}, {%0,%1,%2,%3};"
        : "+f"(c[0]), "+f"(c[1]), "+f"(c[2]), "+f"(c[3])
        : "r"(a[0]), "r"(a[1]), "r"(a[2]), "r"(a[3]), "r"(b[0]), "r"(b[1]));
}

// ---------------- GEMM 128x128, 256 thr, 8 warps (warp tile 64x32) -----------
// C[M,N] = A[M,K(slice)] @ B[N,K(slice)]^T (+res). blockIdx.z = k-split index.
// If gridDim.z > 1, caller passes res=nullptr and C=partials (C + z*M*N).
__global__ void __launch_bounds__(256) gemm128(
    const float* __restrict__ A, const float* __restrict__ Bm,
    const float* __restrict__ res, float* __restrict__ C,
    int M, int N, int K, int Kc) {
    __shared__ uint32_t As[2][128][20];
    __shared__ uint32_t Bs[2][128][20];
    int tid = threadIdx.x, lane = tid & 31, wid = tid >> 5;
    int bm = blockIdx.y * 128, bn = blockIdx.x * 128;
    int wm = (wid & 1) * 64, wn = (wid >> 1) * 32;
    int k0base = blockIdx.z * Kc;
    float* Cw = C + (size_t)blockIdx.z * M * N;

    int lrow = tid >> 1;           // 0..127
    int lkq  = (tid & 1) * 8;      // 0 or 8
    const float* Ag = A + (size_t)(bm + lrow) * K + k0base + lkq;
    const float* Bg = Bm + (size_t)(bn + lrow) * K + k0base + lkq;

    float c[4][4][4] = {};
    int ntiles = Kc >> 4;

    float4 la0, la1, lb0, lb1;
    la0 = *reinterpret_cast<const float4*>(Ag);
    la1 = *reinterpret_cast<const float4*>(Ag + 4);
    lb0 = *reinterpret_cast<const float4*>(Bg);
    lb1 = *reinterpret_cast<const float4*>(Bg + 4);
    As[0][lrow][lkq+0] = f2tf(la0.x); As[0][lrow][lkq+1] = f2tf(la0.y);
    As[0][lrow][lkq+2] = f2tf(la0.z); As[0][lrow][lkq+3] = f2tf(la0.w);
    As[0][lrow][lkq+4] = f2tf(la1.x); As[0][lrow][lkq+5] = f2tf(la1.y);
    As[0][lrow][lkq+6] = f2tf(la1.z); As[0][lrow][lkq+7] = f2tf(la1.w);
    Bs[0][lrow][lkq+0] = f2tf(lb0.x); Bs[0][lrow][lkq+1] = f2tf(lb0.y);
    Bs[0][lrow][lkq+2] = f2tf(lb0.z); Bs[0][lrow][lkq+3] = f2tf(lb0.w);
    Bs[0][lrow][lkq+4] = f2tf(lb1.x); Bs[0][lrow][lkq+5] = f2tf(lb1.y);
    Bs[0][lrow][lkq+6] = f2tf(lb1.z); Bs[0][lrow][lkq+7] = f2tf(lb1.w);
    __syncthreads();

    for (int kt = 0; kt < ntiles; kt++) {
        int cur = kt & 1;
        if (kt + 1 < ntiles) {
            const float* Ap = Ag + (size_t)(kt+1)*16;
            const float* Bp = Bg + (size_t)(kt+1)*16;
            la0 = *reinterpret_cast<const float4*>(Ap);
            la1 = *reinterpret_cast<const float4*>(Ap + 4);
            lb0 = *reinterpret_cast<const float4*>(Bp);
            lb1 = *reinterpret_cast<const float4*>(Bp + 4);
        }
#pragma unroll
        for (int ks = 0; ks < 2; ks++) {
            int kb = ks*8 + (lane & 3);
            int rA = wm + (lane >> 2);
            int rB = wn + (lane >> 2);
            uint32_t a[4][4], b[4][2];
#pragma unroll
            for (int mt = 0; mt < 4; mt++) {
                a[mt][0] = As[cur][rA + mt*16    ][kb];
                a[mt][1] = As[cur][rA + mt*16 + 8][kb];
                a[mt][2] = As[cur][rA + mt*16    ][kb+4];
                a[mt][3] = As[cur][rA + mt*16 + 8][kb+4];
            }
#pragma unroll
            for (int nt = 0; nt < 4; nt++) {
                b[nt][0] = Bs[cur][rB + nt*8][kb];
                b[nt][1] = Bs[cur][rB + nt*8][kb+4];
            }
#pragma unroll
            for (int mt = 0; mt < 4; mt++)
#pragma unroll
                for (int nt = 0; nt < 4; nt++)
                    mma_tf32(c[mt][nt], a[mt], b[nt]);
        }
        if (kt + 1 < ntiles) {
            int nxt = cur ^ 1;
            As[nxt][lrow][lkq+0] = f2tf(la0.x); As[nxt][lrow][lkq+1] = f2tf(la0.y);
            As[nxt][lrow][lkq+2] = f2tf(la0.z); As[nxt][lrow][lkq+3] = f2tf(la0.w);
            As[nxt][lrow][lkq+4] = f2tf(la1.x); As[nxt][lrow][lkq+5] = f2tf(la1.y);
            As[nxt][lrow][lkq+6] = f2tf(la1.z); As[nxt][lrow][lkq+7] = f2tf(la1.w);
            Bs[nxt][lrow][lkq+0] = f2tf(lb0.x); Bs[nxt][lrow][lkq+1] = f2tf(lb0.y);
            Bs[nxt][lrow][lkq+2] = f2tf(lb0.z); Bs[nxt][lrow][lkq+3] = f2tf(lb0.w);
            Bs[nxt][lrow][lkq+4] = f2tf(lb1.x); Bs[nxt][lrow][lkq+5] = f2tf(lb1.y);
            Bs[nxt][lrow][lkq+6] = f2tf(lb1.z); Bs[nxt][lrow][lkq+7] = f2tf(lb1.w);
        }
        __syncthreads();
    }

#pragma unroll
    for (int mt = 0; mt < 4; mt++) {
        int r0 = bm + wm + mt*16 + (lane >> 2);
#pragma unroll
        for (int nt = 0; nt < 4; nt++) {
            int cc = bn + wn + nt*8 + (lane & 3)*2;
            float2 v0 = make_float2(c[mt][nt][0], c[mt][nt][1]);
            float2 v1 = make_float2(c[mt][nt][2], c[mt][nt][3]);
            if (res) {
                float2 q0 = *reinterpret_cast<const float2*>(&res[(size_t)r0*N + cc]);
                float2 q1 = *reinterpret_cast<const float2*>(&res[(size_t)(r0+8)*N + cc]);
                v0.x += q0.x; v0.y += q0.y; v1.x += q1.x; v1.y += q1.y;
            }
            *reinterpret_cast<float2*>(&Cw[(size_t)r0*N + cc]) = v0;
            *reinterpret_cast<float2*>(&Cw[(size_t)(r0+8)*N + cc]) = v1;
        }
    }
}

// ---------------- GEMM 64x64, 128 thr, 4 warps (warp tile 32x32), split-K ----
__global__ void __launch_bounds__(128) gemm64(
    const float* __restrict__ A, const float* __restrict__ Bm,
    float* __restrict__ C, int M, int N, int K, int Kc) {
    __shared__ uint32_t As[2][64][20];
    __shared__ uint32_t Bs[2][64][20];
    int tid = threadIdx.x, lane = tid & 31, wid = tid >> 5;
    int bm = blockIdx.y * 64, bn = blockIdx.x * 64;
    int wm = (wid & 1) * 32, wn = (wid >> 1) * 32;
    int k0base = blockIdx.z * Kc;
    float* Cw = C + (size_t)blockIdx.z * M * N;

    int lrow = tid >> 1;           // 0..63
    int lkq  = (tid & 1) * 8;
    const float* Ag = A + (size_t)(bm + lrow) * K + k0base + lkq;
    const float* Bg = Bm + (size_t)(bn + lrow) * K + k0base + lkq;

    float c[2][4][4] = {};
    int ntiles = Kc >> 4;

    float4 la0, la1, lb0, lb1;
    la0 = *reinterpret_cast<const float4*>(Ag);
    la1 = *reinterpret_cast<const float4*>(Ag + 4);
    lb0 = *reinterpret_cast<const float4*>(Bg);
    lb1 = *reinterpret_cast<const float4*>(Bg + 4);
    As[0][lrow][lkq+0] = f2tf(la0.x); As[0][lrow][lkq+1] = f2tf(la0.y);
    As[0][lrow][lkq+2] = f2tf(la0.z); As[0][lrow][lkq+3] = f2tf(la0.w);
    As[0][lrow][lkq+4] = f2tf(la1.x); As[0][lrow][lkq+5] = f2tf(la1.y);
    As[0][lrow][lkq+6] = f2tf(la1.z); As[0][lrow][lkq+7] = f2tf(la1.w);
    Bs[0][lrow][lkq+0] = f2tf(lb0.x); Bs[0][lrow][lkq+1] = f2tf(lb0.y);
    Bs[0][lrow][lkq+2] = f2tf(lb0.z); Bs[0][lrow][lkq+3] = f2tf(lb0.w);
    Bs[0][lrow][lkq+4] = f2tf(lb1.x); Bs[0][lrow][lkq+5] = f2tf(lb1.y);
    Bs[0][lrow][lkq+6] = f2tf(lb1.z); Bs[0][lrow][lkq+7] = f2tf(lb1.w);
    __syncthreads();

    for (int kt = 0; kt < ntiles; kt++) {
        int cur = kt & 1;
        if (kt + 1 < ntiles) {
            const float* Ap = Ag + (size_t)(kt+1)*16;
            const float* Bp = Bg + (size_t)(kt+1)*16;
            la0 = *reinterpret_cast<const float4*>(Ap);
            la1 = *reinterpret_cast<const float4*>(Ap + 4);
            lb0 = *reinterpret_cast<const float4*>(Bp);
            lb1 = *reinterpret_cast<const float4*>(Bp + 4);
        }
#pragma unroll
        for (int ks = 0; ks < 2; ks++) {
            int kb = ks*8 + (lane & 3);
            int rA = wm + (lane >> 2);
            int rB = wn + (lane >> 2);
            uint32_t a[2][4], b[4][2];
#pragma unroll
            for (int mt = 0; mt < 2; mt++) {
                a[mt][0] = As[cur][rA + mt*16    ][kb];
                a[mt][1] = As[cur][rA + mt*16 + 8][kb];
                a[mt][2] = As[cur][rA + mt*16    ][kb+4];
                a[mt][3] = As[cur][rA + mt*16 + 8][kb+4];
            }
#pragma unroll
            for (int nt = 0; nt < 4; nt++) {
                b[nt][0] = Bs[cur][rB + nt*8][kb];
                b[nt][1] = Bs[cur][rB + nt*8][kb+4];
            }
#pragma unroll
            for (int mt = 0; mt < 2; mt++)
#pragma unroll
                for (int nt = 0; nt < 4; nt++)
                    mma_tf32(c[mt][nt], a[mt], b[nt]);
        }
        if (kt + 1 < ntiles) {
            int nxt = cur ^ 1;
            As[nxt][lrow][lkq+0] = f2tf(la0.x); As[nxt][lrow][lkq+1] = f2tf(la0.y);
            As[nxt][lrow][lkq+2] = f2tf(la0.z); As[nxt][lrow][lkq+3] = f2tf(la0.w);
            As[nxt][lrow][lkq+4] = f2tf(la1.x); As[nxt][lrow][lkq+5] = f2tf(la1.y);
            As[nxt][lrow][lkq+6] = f2tf(la1.z); As[nxt][lrow][lkq+7] = f2tf(la1.w);
            Bs[nxt][lrow][lkq+0] = f2tf(lb0.x); Bs[nxt][lrow][lkq+1] = f2tf(lb0.y);
            Bs[nxt][lrow][lkq+2] = f2tf(lb0.z); Bs[nxt][lrow][lkq+3] = f2tf(lb0.w);
            Bs[nxt][lrow][lkq+4] = f2tf(lb1.x); Bs[nxt][lrow][lkq+5] = f2tf(lb1.y);
            Bs[nxt][lrow][lkq+6] = f2tf(lb1.z); Bs[nxt][lrow][lkq+7] = f2tf(lb1.w);
        }
        __syncthreads();
    }

#pragma unroll
    for (int mt = 0; mt < 2; mt++) {
        int r0 = bm + wm + mt*16 + (lane >> 2);
#pragma unroll
        for (int nt = 0; nt < 4; nt++) {
            int cc = bn + wn + nt*8 + (lane & 3)*2;
            *reinterpret_cast<float2*>(&Cw[(size_t)r0*N + cc]) =
                make_float2(c[mt][nt][0], c[mt][nt][1]);
            *reinterpret_cast<float2*>(&Cw[(size_t)(r0+8)*N + cc]) =
                make_float2(c[mt][nt][2], c[mt][nt][3]);
        }
    }
}

// ---------------- split-K reduce ----------------------------------------------
__global__ void reduce_splitk(const float* __restrict__ part, const float* __restrict__ res,
                              float* __restrict__ out, int MN, int SK) {
    int i = blockIdx.x*256 + threadIdx.x;
    if (i >= MN) return;
    float s = res ? res[i] : 0.f;
    for (int k = 0; k < SK; k++) s += part[(size_t)k*MN + i];
    out[i] = s;
}

// ---------------- fused flash attention (per (b,h), 64-query tiles) ----------
#define ATTN_SMEM (4*64*68*4 + 3*64*4)
__global__ void __launch_bounds__(256) fattn(
    const float* __restrict__ Q, const float* __restrict__ Kg,
    const float* __restrict__ Vg, float* __restrict__ O,
    int lq, int lk, int ldk, int mask_mode, const unsigned char* __restrict__ kpm) {
    extern __shared__ float sm[];
    float (*Qs)[68] = (float(*)[68])sm;
    float (*Ks)[68] = (float(*)[68])(sm + 64*68);
    float (*Vs)[68] = (float(*)[68])(sm + 2*64*68);
    float (*Ps)[68] = (float(*)[68])(sm + 3*64*68);
    float* m_s  = sm + 4*64*68;
    float* l_s  = m_s + 64;
    float* al_s = l_s + 64;

    int tid = threadIdx.x;
    int q0 = blockIdx.x * 64;
    int bh = blockIdx.y;
    int b = bh >> 4, h = bh & 15;

#pragma unroll
    for (int i = 0; i < 4; i++) {
        int id = tid + i*256;
        int r = id >> 4, dq = (id & 15) * 4;
        *reinterpret_cast<float4*>(&Qs[r][dq]) =
            *reinterpret_cast<const float4*>(&Q[((size_t)(b*lq + q0 + r))*Ddim + h*HDdim + dq]);
    }
    if (tid < 64) { m_s[tid] = -INFINITY; l_s[tid] = 0.f; }
    __syncthreads();

    int ty = tid >> 4, tx = tid & 15;
    int r0 = ty * 4;
    float o[4][4] = {};

    int c_lo = 0, c_hi = lk >> 6;
    if (mask_mode) {
        c_lo = (q0 >= WINv) ? (q0 - WINv) >> 6 : 0;
        int hi = (q0 + 64 + WINv) >> 6;
        if (hi < c_hi) c_hi = hi;
    }

    for (int ck = c_lo; ck < c_hi; ck++) {
        int kb = ck * 64;
#pragma unroll
        for (int i = 0; i < 4; i++) {
            int id = tid + i*256;
            int r = id >> 4, dq = (id & 15)*4;
            size_t g = ((size_t)(b*lk + kb + r))*ldk + h*HDdim + dq;
            *reinterpret_cast<float4*>(&Ks[r][dq]) = *reinterpret_cast<const float4*>(&Kg[g]);
            *reinterpret_cast<float4*>(&Vs[r][dq]) = *reinterpret_cast<const float4*>(&Vg[g]);
        }
        __syncthreads();

        float s[4][4] = {};
#pragma unroll
        for (int k = 0; k < 64; k += 4) {
            float4 qv[4], kv[4];
#pragma unroll
            for (int i = 0; i < 4; i++) qv[i] = *reinterpret_cast<float4*>(&Qs[r0+i][k]);
#pragma unroll
            for (int j = 0; j < 4; j++) kv[j] = *reinterpret_cast<float4*>(&Ks[tx + 16*j][k]);
#pragma unroll
            for (int i = 0; i < 4; i++)
#pragma unroll
                for (int j = 0; j < 4; j++)
                    s[i][j] += qv[i].x*kv[j].x + qv[i].y*kv[j].y
                             + qv[i].z*kv[j].z + qv[i].w*kv[j].w;
        }
#pragma unroll
        for (int i = 0; i < 4; i++) {
            int qr = q0 + r0 + i;
#pragma unroll
            for (int j = 0; j < 4; j++) {
                int col = kb + tx + 16*j;
                float v = s[i][j] * 0.125f;
                int jr = col - qr;
                bool ok = true;
                if (mask_mode == 1) ok = (jr <= WINv && jr >= -WINv);
                else if (mask_mode == 2) ok = (jr <= WINv && jr >= -WINv && ((jr & 3) == 0));
                if (kpm && kpm[b*lk + col]) ok = false;
                Ps[r0+i][tx + 16*j] = ok ? v : -INFINITY;
            }
        }
        __syncthreads();

        {
            int w = tid >> 5, ln = tid & 31;
            for (int rr = w*8; rr < w*8 + 8; rr++) {
                float s0 = Ps[rr][ln], s1 = Ps[rr][ln+32];
                float mx = fmaxf(s0, s1);
#pragma unroll
                for (int off = 16; off; off >>= 1)
                    mx = fmaxf(mx, __shfl_xor_sync(0xffffffffu, mx, off));
                float mo = m_s[rr];
                float mn = fmaxf(mo, mx);
                float p0, p1, alpha;
                if (mn == -INFINITY) { p0 = 0.f; p1 = 0.f; alpha = 1.f; }
                else {
                    alpha = __expf(mo - mn);
                    p0 = (s0 == -INFINITY) ? 0.f : __expf(s0 - mn);
                    p1 = (s1 == -INFINITY) ? 0.f : __expf(s1 - mn);
                }
                Ps[rr][ln] = p0; Ps[rr][ln+32] = p1;
                float sum = p0 + p1;
#pragma unroll
                for (int off = 16; off; off >>= 1)
                    sum += __shfl_xor_sync(0xffffffffu, sum, off);
                if (ln == 0) {
                    l_s[rr] = l_s[rr]*alpha + sum;
                    m_s[rr] = mn;
                    al_s[rr] = alpha;
                }
            }
        }
        __syncthreads();

#pragma unroll
        for (int i = 0; i < 4; i++) {
            float a = al_s[r0+i];
#pragma unroll
            for (int j = 0; j < 4; j++) o[i][j] *= a;
        }
#pragma unroll
        for (int k = 0; k < 64; k += 4) {
            float4 pk[4];
#pragma unroll
            for (int i = 0; i < 4; i++) pk[i] = *reinterpret_cast<float4*>(&Ps[r0+i][k]);
#pragma unroll
            for (int kk = 0; kk < 4; kk++) {
                float4 vv = *reinterpret_cast<float4*>(&Vs[k+kk][tx*4]);
#pragma unroll
                for (int i = 0; i < 4; i++) {
                    float p = (kk == 0) ? pk[i].x : (kk == 1) ? pk[i].y : (kk == 2) ? pk[i].z : pk[i].w;
                    o[i][0] += p*vv.x; o[i][1] += p*vv.y; o[i][2] += p*vv.z; o[i][3] += p*vv.w;
                }
            }
        }
        __syncthreads();
    }

#pragma unroll
    for (int i = 0; i < 4; i++) {
        float inv = 1.0f / l_s[r0+i];
        float4 ov = make_float4(o[i][0]*inv, o[i][1]*inv, o[i][2]*inv, o[i][3]*inv);
        *reinterpret_cast<float4*>(&O[((size_t)(b*lq + q0 + r0 + i))*Ddim + h*HDdim + tx*4]) = ov;
    }
}

// ---------------- gated fusion -----------------------------------------------
__global__ void gate_fuse(const float* __restrict__ x, const float* __restrict__ h,
                          const float* __restrict__ o0, const float* __restrict__ o1,
                          const float* __restrict__ o2, const float* __restrict__ o3,
                          const float* __restrict__ gw, const float* __restrict__ gb,
                          float* __restrict__ out) {
    int row = blockIdx.x;
    int tid = threadIdx.x; // 128
    int warp = tid >> 5, lane = tid & 31;
    __shared__ float wsh[4];
    const float* hr = h + (size_t)row * Ddim;
    float p = 0.f;
    const float* gwr = gw + warp * Ddim;
    for (int dd = lane; dd < Ddim; dd += 32) p += hr[dd] * gwr[dd];
#pragma unroll
    for (int off = 16; off; off >>= 1) p += __shfl_down_sync(0xffffffffu, p, off);
    if (lane == 0) wsh[warp] = p + gb[warp];
    __syncthreads();
    if (tid == 0) {
        float mx = fmaxf(fmaxf(wsh[0], wsh[1]), fmaxf(wsh[2], wsh[3]));
        float e0 = expf(wsh[0]-mx), e1 = expf(wsh[1]-mx), e2 = expf(wsh[2]-mx), e3 = expf(wsh[3]-mx);
        float inv = 1.0f / (e0+e1+e2+e3);
        wsh[0] = e0*inv; wsh[1] = e1*inv; wsh[2] = e2*inv; wsh[3] = e3*inv;
    }
    __syncthreads();
    float w0 = wsh[0], w1 = wsh[1], w2 = wsh[2], w3 = wsh[3];
    size_t base = (size_t)row * Ddim;
    for (int dd = tid; dd < Ddim; dd += 128)
        out[base+dd] = x[base+dd] + w0*o0[base+dd] + w1*o1[base+dd]
                                  + w2*o2[base+dd] + w3*o3[base+dd];
}

// ---------------- elementwise helpers ----------------------------------------
__global__ void broadcast_k(const float* __restrict__ src, float* __restrict__ dst,
                            int n, int total) {
    int i = blockIdx.x*256 + threadIdx.x;
    if (i < total) dst[i] = src[i % n];
}
__global__ void ema_k(const float* __restrict__ prev, const float* __restrict__ delta,
                      float* __restrict__ mem, int n) {
    int i = blockIdx.x*256 + threadIdx.x;
    if (i < n) mem[i] = 0.9f*prev[i] + 0.1f*(prev[i] + delta[i]);
}
__global__ void silu_mul_k(const float* __restrict__ u, float* __restrict__ o, int n) {
    int i = blockIdx.x*256 + threadIdx.x;
    if (i < n) {
        int r = i / DFFdim, f = i % DFFdim;
        float a = u[(size_t)r*2*DFFdim + f];
        float g = u[(size_t)r*2*DFFdim + DFFdim + f];
        o[i] = (a / (1.0f + expf(-a))) * g;
    }
}
__global__ void copy_k(const float* __restrict__ src, float* __restrict__ dst, int n) {
    int i = blockIdx.x*256 + threadIdx.x;
    if (i < n) dst[i] = src[i];
}

#define SYMF(name) ({ void* _p = nullptr; cudaGetSymbolAddress(&_p, name); (float*)_p; })

// generic projection: C[M,N] = A @ W^T (+res); picks big/small path
static void proj(const float* A, const float* W, const float* res, float* C,
                 float* partB, int M, int N, int K) {
    if (M >= 1024) {
        gemm128<<<dim3(N/128, M/128, 1), 256>>>(A, W, res, C, M, N, K, K);
    } else {
        const int SK = 4;
        gemm64<<<dim3(N/64, M/64, SK), 128>>>(A, W, partB, M, N, K, K/SK);
        int MN = M*N;
        reduce_splitk<<<(MN+255)/256, 256>>>(partB, res, C, MN, SK);
    }
}

// ---------------- host-side MHA orchestration --------------------------------
static void run_mha(const float* qin, const float* kvin, const float* w,
                    int lq, int lk, int mask_mode, const unsigned char* kpm,
                    const float* res, float* out,
                    float* Qb, float* KVb, float* Ob, float* partB) {
    const float* Wq = w;
    const float* Wkv = w + Ddim*Ddim;         // Wk || Wv contiguous, 2048 x 1024
    const float* Wo = w + 3*Ddim*Ddim;
    int Mq = Bdim * lq, Mk = Bdim * lk;
    proj(qin, Wq, nullptr, Qb, partB, Mq, Ddim, Ddim);
    proj(kvin, Wkv, nullptr, KVb, partB, Mk, 2*Ddim, Ddim);
    fattn<<<dim3(lq/64, Bdim*Hdim), 256, ATTN_SMEM>>>(Qb, KVb, KVb + Ddim, Ob,
                                                      lq, lk, 2*Ddim, mask_mode, kpm);
    proj(Ob, Wo, res, out, partB, Mq, Ddim, Ddim);
}

extern "C" void kernel_launch(void* const* d_in, const int* in_sizes, int n_in,
                              void* d_out, int out_size) {
    const float* x          = (const float*)d_in[0];
    const unsigned char* kpm = (const unsigned char*)d_in[1];
    const float* norm_w     = (const float*)d_in[2];
    const float* ld_nq      = (const float*)d_in[3];
    const float* ld_nk      = (const float*)d_in[4];
    const float* local_w    = (const float*)d_in[5];
    const float* dil_w      = (const float*)d_in[6];
    const float* lat_tokens = (const float*)d_in[7];
    const float* lp_nq      = (const float*)d_in[8];
    const float* lp_nk      = (const float*)d_in[9];
    const float* lat_to_w   = (const float*)d_in[10];
    const float* lat_from_w = (const float*)d_in[11];
    const float* mem_tokens = (const float*)d_in[12];
    const float* mem_nq     = (const float*)d_in[13];
    const float* mem_nk     = (const float*)d_in[14];
    const float* mem_read_w = (const float*)d_in[15];
    const float* mem_write_w= (const float*)d_in[16];
    const float* gate_w     = (const float*)d_in[17];
    const float* gate_b     = (const float*)d_in[18];
    const float* up_w       = (const float*)d_in[19];
    const float* down_w     = (const float*)d_in[20];
    float* out = (float*)d_out;

    cudaFuncSetAttribute(fattn, cudaFuncAttributeMaxDynamicSharedMemorySize, ATTN_SMEM);

    float* hB   = SYMF(g_h);
    float* qnB  = SYMF(g_qn);
    float* knB  = SYMF(g_kn);
    float* QB   = SYMF(g_Q);
    float* KVB  = SYMF(g_KV);
    float* OB   = SYMF(g_O);
    float* oLB  = SYMF(g_oL);
    float* oDB  = SYMF(g_oD);
    float* xlatB= SYMF(g_xlat);
    float* xmemB= SYMF(g_xmem);
    float* x1B  = SYMF(g_x1);
    float* hnB  = SYMF(g_hn);
    float* latprevB = SYMF(g_latprev);
    float* latB  = SYMF(g_lat);
    float* latqB = SYMF(g_latq);
    float* latkB = SYMF(g_latk);
    float* memprevB = SYMF(g_memprev);
    float* memB  = SYMF(g_mem);
    float* memqB = SYMF(g_memq);
    float* memkB = SYMF(g_memk);
    float* memdB = SYMF(g_memdelta);
    float* uB    = SYMF(g_u);
    float* gactB = SYMF(g_gact);
    float* partB = SYMF(g_part);

    const int rowsBL = Bdim * Ldim;

    rmsnorm_k<<<rowsBL, 256>>>(x, norm_w, hB);

    // local + dilated branches (shared q/k norms)
    rmsnorm_k<<<rowsBL, 256>>>(hB, ld_nq, qnB);
    rmsnorm_k<<<rowsBL, 256>>>(hB, ld_nk, knB);
    run_mha(qnB, knB, local_w, Ldim, Ldim, 1, kpm, nullptr, oLB, QB, KVB, OB, partB);
    run_mha(qnB, knB, dil_w,   Ldim, Ldim, 2, kpm, nullptr, oDB, QB, KVB, OB, partB);

    // latent pool
    broadcast_k<<<(BKD+255)/256, 256>>>(lat_tokens, latprevB, KLAT*Ddim, BKD);
    rmsnorm_k<<<Bdim*KLAT, 256>>>(latprevB, lp_nq, latqB);
    rmsnorm_k<<<rowsBL, 256>>>(hB, lp_nk, knB);
    run_mha(latqB, knB, lat_to_w, KLAT, Ldim, 0, kpm, latprevB, latB, QB, KVB, OB, partB);
    rmsnorm_k<<<rowsBL, 256>>>(hB, lp_nq, qnB);
    rmsnorm_k<<<Bdim*KLAT, 256>>>(latB, lp_nk, latkB);
    run_mha(qnB, latkB, lat_from_w, Ldim, KLAT, 0, nullptr, hB, xlatB, QB, KVB, OB, partB);

    // infini-memory
    broadcast_k<<<(BMD+255)/256, 256>>>(mem_tokens, memprevB, MMEM*Ddim, BMD);
    rmsnorm_k<<<Bdim*MMEM, 256>>>(memprevB, mem_nq, memqB);
    rmsnorm_k<<<rowsBL, 256>>>(hB, mem_nk, knB);
    run_mha(memqB, knB, mem_write_w, MMEM, Ldim, 0, kpm, nullptr, memdB, QB, KVB, OB, partB);
    ema_k<<<(BMD+255)/256, 256>>>(memprevB, memdB, memB, BMD);
    rmsnorm_k<<<rowsBL, 256>>>(hB, mem_nq, qnB);
    rmsnorm_k<<<Bdim*MMEM, 256>>>(memB, mem_nk, memkB);
    run_mha(qnB, memkB, mem_read_w, Ldim, MMEM, 0, nullptr, hB, xmemB, QB, KVB, OB, partB);

    // gated fusion
    gate_fuse<<<rowsBL, 128>>>(x, hB, oLB, oDB, xlatB, xmemB, gate_w, gate_b, x1B);

    // SwiGLU FFN
    rmsnorm_k<<<rowsBL, 256>>>(x1B, norm_w, hnB);
    gemm128<<<dim3(2*DFFdim/128, rowsBL/128, 1), 256>>>(hnB, up_w, nullptr, uB,
                                                        rowsBL, 2*DFFdim, Ddim, Ddim);
    int nact = rowsBL * DFFdim;
    silu_mul_k<<<(nact+255)/256, 256>>>(uB, gactB, nact);
    // down proj split-K=2 for full-chip fill
    gemm128<<<dim3(Ddim/128, rowsBL/128, 2), 256>>>(gactB, down_w, nullptr, partB,
                                                    rowsBL, Ddim, DFFdim, DFFdim/2);
    reduce_splitk<<<(BLD+255)/256, 256>>>(partB, x1B, out, BLD, 2);

    // lat + mem outputs
    copy_k<<<(BKD+255)/256, 256>>>(latB, out + (size_t)BLD, BKD);
    copy_k<<<(BMD+255)/256, 256>>>(memB, out + (size_t)BLD + BKD, BMD);
}

// round 4
// speedup vs baseline: 5.5861x; 1.1010x over previous
#include <cuda_runtime.h>
#include <math.h>
#include <stdint.h>

#define Bdim 2
#define Ldim 1024
#define Ddim 1024
#define Hdim 16
#define HDdim 64
#define DFFdim 4096
#define WINv 128
#define DILv 4
#define KLAT 64
#define MMEM 64
#define EPSV 1e-6f

#define BLD (Bdim*Ldim*Ddim)
#define BKD (Bdim*KLAT*Ddim)
#define BMD (Bdim*MMEM*Ddim)

// ---------------- scratch (static device memory; no allocations) -------------
__device__ float g_h[BLD];
__device__ float g_qn[BLD];
__device__ float g_kn[BLD];
__device__ float g_Q[BLD];
__device__ float g_KV[(size_t)Bdim*Ldim*2*Ddim];       // fused K||V, 16 MB
__device__ float g_O[BLD];
__device__ float g_oL[BLD];
__device__ float g_oD[BLD];
__device__ float g_xlat[BLD];
__device__ float g_xmem[BLD];
__device__ float g_x1[BLD];
__device__ float g_hn[BLD];
__device__ float g_latprev[BKD];
__device__ float g_lat[BKD];
__device__ float g_latq[BKD];
__device__ float g_latk[BKD];
__device__ float g_memprev[BMD];
__device__ float g_mem[BMD];
__device__ float g_memq[BMD];
__device__ float g_memk[BMD];
__device__ float g_memdelta[BMD];
__device__ float g_u[(size_t)Bdim*Ldim*2*DFFdim];      // 64 MB
__device__ float g_gact[(size_t)Bdim*Ldim*DFFdim];     // 32 MB
__device__ float g_part[(size_t)2048*1024*2];          // split-K partials, 16 MB

// ---------------- rmsnorm ----------------------------------------------------
__global__ void rmsnorm_k(const float* __restrict__ x, const float* __restrict__ w,
                          float* __restrict__ o) {
    int row = blockIdx.x;
    const float* xr = x + (size_t)row * Ddim;
    float* orow = o + (size_t)row * Ddim;
    int tid = threadIdx.x;          // 256 threads
    float v[4];
    float s = 0.f;
#pragma unroll
    for (int i = 0; i < 4; i++) { v[i] = xr[tid + i*256]; s += v[i]*v[i]; }
    __shared__ float red[8];
#pragma unroll
    for (int off = 16; off; off >>= 1) s += __shfl_xor_sync(0xffffffffu, s, off);
    if ((tid & 31) == 0) red[tid >> 5] = s;
    __syncthreads();
    float tot = 0.f;
#pragma unroll
    for (int i = 0; i < 8; i++) tot += red[i];
    float scale = rsqrtf(tot * (1.0f/Ddim) + EPSV);
#pragma unroll
    for (int i = 0; i < 4; i++) orow[tid + i*256] = w[tid + i*256] * (v[i] * scale);
}

// ---------------- tf32 mma helpers -------------------------------------------
__device__ __forceinline__ uint32_t f2tf(float f) {
    uint32_t u;
    asm("cvt.rna.tf32.f32 %0, %1;" : "=r"(u) : "f"(f));
    return u;
}
__device__ __forceinline__ void mma_tf32(float* c, const uint32_t* a, const uint32_t* b) {
    asm volatile("mma.sync.aligned.m16n8k8.row.col.f32.tf32.tf32.f32 "
        "{%0,%1,%2,%3}, {%4,%5,%6,%7}, {%8,%9}, {%0,%1,%2,%3};"
        : "+f"(c[0]), "+f"(c[1]), "+f"(c[2]), "+f"(c[3])
        : "r"(a[0]), "r"(a[1]), "r"(a[2]), "r"(a[3]), "r"(b[0]), "r"(b[1]));
}
__device__ __forceinline__ void cp16(uint32_t dst, const void* src) {
    asm volatile("cp.async.cg.shared.global [%0], [%1], 16;" :: "r"(dst), "l"(src));
}
__device__ __forceinline__ void cp_commit() {
    asm volatile("cp.async.commit_group;");
}
template <int N>
__device__ __forceinline__ void cp_wait() {
    asm volatile("cp.async.wait_group %0;" :: "n"(N));
}

// ---------------- GEMM 128x128, 256 thr, cp.async 3-stage --------------------
// C[M,N] = A[M,K(slice)] @ B[N,K(slice)]^T (+res). blockIdx.z = k-split index.
// Raw fp32 bits fed to mma.tf32 (HW truncates to tf32).
#define GSTAGE 3
#define GTILEF (128*20)             // floats per stage per matrix
#define GEMM_SMEM (GSTAGE*GTILEF*2*4)
__global__ void __launch_bounds__(256, 2) gemm128(
    const float* __restrict__ A, const float* __restrict__ Bm,
    const float* __restrict__ res, float* __restrict__ C,
    int M, int N, int K, int Kc) {
    extern __shared__ float smg[];
    float* As = smg;                      // [GSTAGE][128][20]
    float* Bs = smg + GSTAGE*GTILEF;
    int tid = threadIdx.x, lane = tid & 31, wid = tid >> 5;
    int bm = blockIdx.y * 128, bn = blockIdx.x * 128;
    int wm = (wid & 1) * 64, wn = (wid >> 1) * 32;
    int k0base = blockIdx.z * Kc;
    float* Cw = C + (size_t)blockIdx.z * M * N;

    int lrow = tid >> 1;           // 0..127
    int lkq  = (tid & 1) * 8;      // 0 or 8
    const float* Ag = A + (size_t)(bm + lrow) * K + k0base + lkq;
    const float* Bg = Bm + (size_t)(bn + lrow) * K + k0base + lkq;
    uint32_t sA = (uint32_t)__cvta_generic_to_shared(As) + (lrow*20 + lkq)*4;
    uint32_t sB = (uint32_t)__cvta_generic_to_shared(Bs) + (lrow*20 + lkq)*4;

    float c[4][4][4] = {};
    int ntiles = Kc >> 4;

    // prologue: stages 0,1
    {
        cp16(sA, Ag); cp16(sA + 16, Ag + 4);
        cp16(sB, Bg); cp16(sB + 16, Bg + 4);
        cp_commit();
        if (ntiles > 1) {
            cp16(sA + GTILEF*4, Ag + 16); cp16(sA + GTILEF*4 + 16, Ag + 20);
            cp16(sB + GTILEF*4, Bg + 16); cp16(sB + GTILEF*4 + 16, Bg + 20);
        }
        cp_commit();
    }

    for (int kt = 0; kt < ntiles; kt++) {
        cp_wait<1>();
        __syncthreads();
        // issue stage kt+2 (overwrites stage (kt-1)%3, protected by the sync)
        if (kt + 2 < ntiles) {
            int s = (kt + 2) % GSTAGE;
            const float* Ap = Ag + (size_t)(kt+2)*16;
            const float* Bp = Bg + (size_t)(kt+2)*16;
            cp16(sA + s*GTILEF*4, Ap); cp16(sA + s*GTILEF*4 + 16, Ap + 4);
            cp16(sB + s*GTILEF*4, Bp); cp16(sB + s*GTILEF*4 + 16, Bp + 4);
        }
        cp_commit();

        const float* Ac = As + (kt % GSTAGE) * GTILEF;
        const float* Bc = Bs + (kt % GSTAGE) * GTILEF;
#pragma unroll
        for (int ks = 0; ks < 2; ks++) {
            int kb = ks*8 + (lane & 3);
            int rA = wm + (lane >> 2);
            int rB = wn + (lane >> 2);
            uint32_t a[4][4], b[4][2];
#pragma unroll
            for (int mt = 0; mt < 4; mt++) {
                a[mt][0] = __float_as_uint(Ac[(rA + mt*16    )*20 + kb]);
                a[mt][1] = __float_as_uint(Ac[(rA + mt*16 + 8)*20 + kb]);
                a[mt][2] = __float_as_uint(Ac[(rA + mt*16    )*20 + kb+4]);
                a[mt][3] = __float_as_uint(Ac[(rA + mt*16 + 8)*20 + kb+4]);
            }
#pragma unroll
            for (int nt = 0; nt < 4; nt++) {
                b[nt][0] = __float_as_uint(Bc[(rB + nt*8)*20 + kb]);
                b[nt][1] = __float_as_uint(Bc[(rB + nt*8)*20 + kb+4]);
            }
#pragma unroll
            for (int mt = 0; mt < 4; mt++)
#pragma unroll
                for (int nt = 0; nt < 4; nt++)
                    mma_tf32(c[mt][nt], a[mt], b[nt]);
        }
        __syncthreads();
    }

#pragma unroll
    for (int mt = 0; mt < 4; mt++) {
        int r0 = bm + wm + mt*16 + (lane >> 2);
#pragma unroll
        for (int nt = 0; nt < 4; nt++) {
            int cc = bn + wn + nt*8 + (lane & 3)*2;
            float2 v0 = make_float2(c[mt][nt][0], c[mt][nt][1]);
            float2 v1 = make_float2(c[mt][nt][2], c[mt][nt][3]);
            if (res) {
                float2 q0 = *reinterpret_cast<const float2*>(&res[(size_t)r0*N + cc]);
                float2 q1 = *reinterpret_cast<const float2*>(&res[(size_t)(r0+8)*N + cc]);
                v0.x += q0.x; v0.y += q0.y; v1.x += q1.x; v1.y += q1.y;
            }
            *reinterpret_cast<float2*>(&Cw[(size_t)r0*N + cc]) = v0;
            *reinterpret_cast<float2*>(&Cw[(size_t)(r0+8)*N + cc]) = v1;
        }
    }
}

// ---------------- GEMM 64x64, 128 thr, 4 warps (warp tile 32x32), split-K ----
__global__ void __launch_bounds__(128) gemm64(
    const float* __restrict__ A, const float* __restrict__ Bm,
    float* __restrict__ C, int M, int N, int K, int Kc) {
    __shared__ uint32_t As[2][64][20];
    __shared__ uint32_t Bs[2][64][20];
    int tid = threadIdx.x, lane = tid & 31, wid = tid >> 5;
    int bm = blockIdx.y * 64, bn = blockIdx.x * 64;
    int wm = (wid & 1) * 32, wn = (wid >> 1) * 32;
    int k0base = blockIdx.z * Kc;
    float* Cw = C + (size_t)blockIdx.z * M * N;

    int lrow = tid >> 1;           // 0..63
    int lkq  = (tid & 1) * 8;
    const float* Ag = A + (size_t)(bm + lrow) * K + k0base + lkq;
    const float* Bg = Bm + (size_t)(bn + lrow) * K + k0base + lkq;

    float c[2][4][4] = {};
    int ntiles = Kc >> 4;

    float4 la0, la1, lb0, lb1;
    la0 = *reinterpret_cast<const float4*>(Ag);
    la1 = *reinterpret_cast<const float4*>(Ag + 4);
    lb0 = *reinterpret_cast<const float4*>(Bg);
    lb1 = *reinterpret_cast<const float4*>(Bg + 4);
    As[0][lrow][lkq+0] = f2tf(la0.x); As[0][lrow][lkq+1] = f2tf(la0.y);
    As[0][lrow][lkq+2] = f2tf(la0.z); As[0][lrow][lkq+3] = f2tf(la0.w);
    As[0][lrow][lkq+4] = f2tf(la1.x); As[0][lrow][lkq+5] = f2tf(la1.y);
    As[0][lrow][lkq+6] = f2tf(la1.z); As[0][lrow][lkq+7] = f2tf(la1.w);
    Bs[0][lrow][lkq+0] = f2tf(lb0.x); Bs[0][lrow][lkq+1] = f2tf(lb0.y);
    Bs[0][lrow][lkq+2] = f2tf(lb0.z); Bs[0][lrow][lkq+3] = f2tf(lb0.w);
    Bs[0][lrow][lkq+4] = f2tf(lb1.x); Bs[0][lrow][lkq+5] = f2tf(lb1.y);
    Bs[0][lrow][lkq+6] = f2tf(lb1.z); Bs[0][lrow][lkq+7] = f2tf(lb1.w);
    __syncthreads();

    for (int kt = 0; kt < ntiles; kt++) {
        int cur = kt & 1;
        if (kt + 1 < ntiles) {
            const float* Ap = Ag + (size_t)(kt+1)*16;
            const float* Bp = Bg + (size_t)(kt+1)*16;
            la0 = *reinterpret_cast<const float4*>(Ap);
            la1 = *reinterpret_cast<const float4*>(Ap + 4);
            lb0 = *reinterpret_cast<const float4*>(Bp);
            lb1 = *reinterpret_cast<const float4*>(Bp + 4);
        }
#pragma unroll
        for (int ks = 0; ks < 2; ks++) {
            int kb = ks*8 + (lane & 3);
            int rA = wm + (lane >> 2);
            int rB = wn + (lane >> 2);
            uint32_t a[2][4], b[4][2];
#pragma unroll
            for (int mt = 0; mt < 2; mt++) {
                a[mt][0] = As[cur][rA + mt*16    ][kb];
                a[mt][1] = As[cur][rA + mt*16 + 8][kb];
                a[mt][2] = As[cur][rA + mt*16    ][kb+4];
                a[mt][3] = As[cur][rA + mt*16 + 8][kb+4];
            }
#pragma unroll
            for (int nt = 0; nt < 4; nt++) {
                b[nt][0] = Bs[cur][rB + nt*8][kb];
                b[nt][1] = Bs[cur][rB + nt*8][kb+4];
            }
#pragma unroll
            for (int mt = 0; mt < 2; mt++)
#pragma unroll
                for (int nt = 0; nt < 4; nt++)
                    mma_tf32(c[mt][nt], a[mt], b[nt]);
        }
        if (kt + 1 < ntiles) {
            int nxt = cur ^ 1;
            As[nxt][lrow][lkq+0] = f2tf(la0.x); As[nxt][lrow][lkq+1] = f2tf(la0.y);
            As[nxt][lrow][lkq+2] = f2tf(la0.z); As[nxt][lrow][lkq+3] = f2tf(la0.w);
            As[nxt][lrow][lkq+4] = f2tf(la1.x); As[nxt][lrow][lkq+5] = f2tf(la1.y);
            As[nxt][lrow][lkq+6] = f2tf(la1.z); As[nxt][lrow][lkq+7] = f2tf(la1.w);
            Bs[nxt][lrow][lkq+0] = f2tf(lb0.x); Bs[nxt][lrow][lkq+1] = f2tf(lb0.y);
            Bs[nxt][lrow][lkq+2] = f2tf(lb0.z); Bs[nxt][lrow][lkq+3] = f2tf(lb0.w);
            Bs[nxt][lrow][lkq+4] = f2tf(lb1.x); Bs[nxt][lrow][lkq+5] = f2tf(lb1.y);
            Bs[nxt][lrow][lkq+6] = f2tf(lb1.z); Bs[nxt][lrow][lkq+7] = f2tf(lb1.w);
        }
        __syncthreads();
    }

#pragma unroll
    for (int mt = 0; mt < 2; mt++) {
        int r0 = bm + wm + mt*16 + (lane >> 2);
#pragma unroll
        for (int nt = 0; nt < 4; nt++) {
            int cc = bn + wn + nt*8 + (lane & 3)*2;
            *reinterpret_cast<float2*>(&Cw[(size_t)r0*N + cc]) =
                make_float2(c[mt][nt][0], c[mt][nt][1]);
            *reinterpret_cast<float2*>(&Cw[(size_t)(r0+8)*N + cc]) =
                make_float2(c[mt][nt][2], c[mt][nt][3]);
        }
    }
}

// ---------------- split-K reduce ----------------------------------------------
__global__ void reduce_splitk(const float* __restrict__ part, const float* __restrict__ res,
                              float* __restrict__ out, int MN, int SK) {
    int i = blockIdx.x*256 + threadIdx.x;
    if (i >= MN) return;
    float s = res ? res[i] : 0.f;
    for (int k = 0; k < SK; k++) s += part[(size_t)k*MN + i];
    out[i] = s;
}

// ---------------- fused flash attention (per (b,h), 64-query tiles) ----------
#define ATTN_SMEM (4*64*68*4 + 3*64*4)
__global__ void __launch_bounds__(256) fattn(
    const float* __restrict__ Q, const float* __restrict__ Kg,
    const float* __restrict__ Vg, float* __restrict__ O,
    int lq, int lk, int ldk, int mask_mode, const unsigned char* __restrict__ kpm) {
    extern __shared__ float sm[];
    float (*Qs)[68] = (float(*)[68])sm;
    float (*Ks)[68] = (float(*)[68])(sm + 64*68);
    float (*Vs)[68] = (float(*)[68])(sm + 2*64*68);
    float (*Ps)[68] = (float(*)[68])(sm + 3*64*68);
    float* m_s  = sm + 4*64*68;
    float* l_s  = m_s + 64;
    float* al_s = l_s + 64;

    int tid = threadIdx.x;
    int q0 = blockIdx.x * 64;
    int bh = blockIdx.y;
    int b = bh >> 4, h = bh & 15;

#pragma unroll
    for (int i = 0; i < 4; i++) {
        int id = tid + i*256;
        int r = id >> 4, dq = (id & 15) * 4;
        *reinterpret_cast<float4*>(&Qs[r][dq]) =
            *reinterpret_cast<const float4*>(&Q[((size_t)(b*lq + q0 + r))*Ddim + h*HDdim + dq]);
    }
    if (tid < 64) { m_s[tid] = -INFINITY; l_s[tid] = 0.f; }
    __syncthreads();

    int ty = tid >> 4, tx = tid & 15;
    int r0 = ty * 4;
    float o[4][4] = {};

    int c_lo = 0, c_hi = lk >> 6;
    if (mask_mode) {
        c_lo = (q0 >= WINv) ? (q0 - WINv) >> 6 : 0;
        int hi = (q0 + 64 + WINv) >> 6;
        if (hi < c_hi) c_hi = hi;
    }

    for (int ck = c_lo; ck < c_hi; ck++) {
        int kb = ck * 64;
#pragma unroll
        for (int i = 0; i < 4; i++) {
            int id = tid + i*256;
            int r = id >> 4, dq = (id & 15)*4;
            size_t g = ((size_t)(b*lk + kb + r))*ldk + h*HDdim + dq;
            *reinterpret_cast<float4*>(&Ks[r][dq]) = *reinterpret_cast<const float4*>(&Kg[g]);
            *reinterpret_cast<float4*>(&Vs[r][dq]) = *reinterpret_cast<const float4*>(&Vg[g]);
        }
        __syncthreads();

        float s[4][4] = {};
#pragma unroll
        for (int k = 0; k < 64; k += 4) {
            float4 qv[4], kv[4];
#pragma unroll
            for (int i = 0; i < 4; i++) qv[i] = *reinterpret_cast<float4*>(&Qs[r0+i][k]);
#pragma unroll
            for (int j = 0; j < 4; j++) kv[j] = *reinterpret_cast<float4*>(&Ks[tx + 16*j][k]);
#pragma unroll
            for (int i = 0; i < 4; i++)
#pragma unroll
                for (int j = 0; j < 4; j++)
                    s[i][j] += qv[i].x*kv[j].x + qv[i].y*kv[j].y
                             + qv[i].z*kv[j].z + qv[i].w*kv[j].w;
        }
#pragma unroll
        for (int i = 0; i < 4; i++) {
            int qr = q0 + r0 + i;
#pragma unroll
            for (int j = 0; j < 4; j++) {
                int col = kb + tx + 16*j;
                float v = s[i][j] * 0.125f;
                int jr = col - qr;
                bool ok = true;
                if (mask_mode == 1) ok = (jr <= WINv && jr >= -WINv);
                else if (mask_mode == 2) ok = (jr <= WINv && jr >= -WINv && ((jr & 3) == 0));
                if (kpm && kpm[b*lk + col]) ok = false;
                Ps[r0+i][tx + 16*j] = ok ? v : -INFINITY;
            }
        }
        __syncthreads();

        {
            int w = tid >> 5, ln = tid & 31;
            for (int rr = w*8; rr < w*8 + 8; rr++) {
                float s0 = Ps[rr][ln], s1 = Ps[rr][ln+32];
                float mx = fmaxf(s0, s1);
#pragma unroll
                for (int off = 16; off; off >>= 1)
                    mx = fmaxf(mx, __shfl_xor_sync(0xffffffffu, mx, off));
                float mo = m_s[rr];
                float mn = fmaxf(mo, mx);
                float p0, p1, alpha;
                if (mn == -INFINITY) { p0 = 0.f; p1 = 0.f; alpha = 1.f; }
                else {
                    alpha = __expf(mo - mn);
                    p0 = (s0 == -INFINITY) ? 0.f : __expf(s0 - mn);
                    p1 = (s1 == -INFINITY) ? 0.f : __expf(s1 - mn);
                }
                Ps[rr][ln] = p0; Ps[rr][ln+32] = p1;
                float sum = p0 + p1;
#pragma unroll
                for (int off = 16; off; off >>= 1)
                    sum += __shfl_xor_sync(0xffffffffu, sum, off);
                if (ln == 0) {
                    l_s[rr] = l_s[rr]*alpha + sum;
                    m_s[rr] = mn;
                    al_s[rr] = alpha;
                }
            }
        }
        __syncthreads();

#pragma unroll
        for (int i = 0; i < 4; i++) {
            float a = al_s[r0+i];
#pragma unroll
            for (int j = 0; j < 4; j++) o[i][j] *= a;
        }
#pragma unroll
        for (int k = 0; k < 64; k += 4) {
            float4 pk[4];
#pragma unroll
            for (int i = 0; i < 4; i++) pk[i] = *reinterpret_cast<float4*>(&Ps[r0+i][k]);
#pragma unroll
            for (int kk = 0; kk < 4; kk++) {
                float4 vv = *reinterpret_cast<float4*>(&Vs[k+kk][tx*4]);
#pragma unroll
                for (int i = 0; i < 4; i++) {
                    float p = (kk == 0) ? pk[i].x : (kk == 1) ? pk[i].y : (kk == 2) ? pk[i].z : pk[i].w;
                    o[i][0] += p*vv.x; o[i][1] += p*vv.y; o[i][2] += p*vv.z; o[i][3] += p*vv.w;
                }
            }
        }
        __syncthreads();
    }

#pragma unroll
    for (int i = 0; i < 4; i++) {
        float inv = 1.0f / l_s[r0+i];
        float4 ov = make_float4(o[i][0]*inv, o[i][1]*inv, o[i][2]*inv, o[i][3]*inv);
        *reinterpret_cast<float4*>(&O[((size_t)(b*lq + q0 + r0 + i))*Ddim + h*HDdim + tx*4]) = ov;
    }
}

// ---------------- gated fusion -----------------------------------------------
__global__ void gate_fuse(const float* __restrict__ x, const float* __restrict__ h,
                          const float* __restrict__ o0, const float* __restrict__ o1,
                          const float* __restrict__ o2, const float* __restrict__ o3,
                          const float* __restrict__ gw, const float* __restrict__ gb,
                          float* __restrict__ out) {
    int row = blockIdx.x;
    int tid = threadIdx.x; // 128
    int warp = tid >> 5, lane = tid & 31;
    __shared__ float wsh[4];
    const float* hr = h + (size_t)row * Ddim;
    float p = 0.f;
    const float* gwr = gw + warp * Ddim;
    for (int dd = lane; dd < Ddim; dd += 32) p += hr[dd] * gwr[dd];
#pragma unroll
    for (int off = 16; off; off >>= 1) p += __shfl_down_sync(0xffffffffu, p, off);
    if (lane == 0) wsh[warp] = p + gb[warp];
    __syncthreads();
    if (tid == 0) {
        float mx = fmaxf(fmaxf(wsh[0], wsh[1]), fmaxf(wsh[2], wsh[3]));
        float e0 = expf(wsh[0]-mx), e1 = expf(wsh[1]-mx), e2 = expf(wsh[2]-mx), e3 = expf(wsh[3]-mx);
        float inv = 1.0f / (e0+e1+e2+e3);
        wsh[0] = e0*inv; wsh[1] = e1*inv; wsh[2] = e2*inv; wsh[3] = e3*inv;
    }
    __syncthreads();
    float w0 = wsh[0], w1 = wsh[1], w2 = wsh[2], w3 = wsh[3];
    size_t base = (size_t)row * Ddim;
    for (int dd = tid; dd < Ddim; dd += 128)
        out[base+dd] = x[base+dd] + w0*o0[base+dd] + w1*o1[base+dd]
                                  + w2*o2[base+dd] + w3*o3[base+dd];
}

// ---------------- elementwise helpers ----------------------------------------
__global__ void broadcast_k(const float* __restrict__ src, float* __restrict__ dst,
                            int n, int total) {
    int i = blockIdx.x*256 + threadIdx.x;
    if (i < total) dst[i] = src[i % n];
}
__global__ void ema_k(const float* __restrict__ prev, const float* __restrict__ delta,
                      float* __restrict__ mem, int n) {
    int i = blockIdx.x*256 + threadIdx.x;
    if (i < n) mem[i] = 0.9f*prev[i] + 0.1f*(prev[i] + delta[i]);
}
__global__ void silu_mul_k(const float* __restrict__ u, float* __restrict__ o, int n) {
    int i = blockIdx.x*256 + threadIdx.x;
    if (i < n) {
        int r = i / DFFdim, f = i % DFFdim;
        float a = u[(size_t)r*2*DFFdim + f];
        float g = u[(size_t)r*2*DFFdim + DFFdim + f];
        o[i] = (a / (1.0f + expf(-a))) * g;
    }
}
__global__ void copy_k(const float* __restrict__ src, float* __restrict__ dst, int n) {
    int i = blockIdx.x*256 + threadIdx.x;
    if (i < n) dst[i] = src[i];
}

#define SYMF(name) ({ void* _p = nullptr; cudaGetSymbolAddress(&_p, name); (float*)_p; })

// generic projection: C[M,N] = A @ W^T (+res); picks path by shape
static void proj(const float* A, const float* W, const float* res, float* C,
                 float* partB, int M, int N, int K) {
    if (M >= 1024) {
        if (N == 1024 && K >= 512) {
            // split-K=2 to fill the chip (grid 256 at 2 CTA/SM)
            gemm128<<<dim3(N/128, M/128, 2), 256, GEMM_SMEM>>>(A, W, nullptr, partB, M, N, K, K/2);
            reduce_splitk<<<(M*N+255)/256, 256>>>(partB, res, C, M*N, 2);
        } else {
            gemm128<<<dim3(N/128, M/128, 1), 256, GEMM_SMEM>>>(A, W, res, C, M, N, K, K);
        }
    } else {
        const int SK = 4;
        gemm64<<<dim3(N/64, M/64, SK), 128>>>(A, W, partB, M, N, K, K/SK);
        int MN = M*N;
        reduce_splitk<<<(MN+255)/256, 256>>>(partB, res, C, MN, SK);
    }
}

// ---------------- host-side MHA orchestration --------------------------------
static void run_mha(const float* qin, const float* kvin, const float* w,
                    int lq, int lk, int mask_mode, const unsigned char* kpm,
                    const float* res, float* out,
                    float* Qb, float* KVb, float* Ob, float* partB) {
    const float* Wq = w;
    const float* Wkv = w + Ddim*Ddim;         // Wk || Wv contiguous, 2048 x 1024
    const float* Wo = w + 3*Ddim*Ddim;
    int Mq = Bdim * lq, Mk = Bdim * lk;
    proj(qin, Wq, nullptr, Qb, partB, Mq, Ddim, Ddim);
    proj(kvin, Wkv, nullptr, KVb, partB, Mk, 2*Ddim, Ddim);
    fattn<<<dim3(lq/64, Bdim*Hdim), 256, ATTN_SMEM>>>(Qb, KVb, KVb + Ddim, Ob,
                                                      lq, lk, 2*Ddim, mask_mode, kpm);
    proj(Ob, Wo, res, out, partB, Mq, Ddim, Ddim);
}

extern "C" void kernel_launch(void* const* d_in, const int* in_sizes, int n_in,
                              void* d_out, int out_size) {
    const float* x          = (const float*)d_in[0];
    const unsigned char* kpm = (const unsigned char*)d_in[1];
    const float* norm_w     = (const float*)d_in[2];
    const float* ld_nq      = (const float*)d_in[3];
    const float* ld_nk      = (const float*)d_in[4];
    const float* local_w    = (const float*)d_in[5];
    const float* dil_w      = (const float*)d_in[6];
    const float* lat_tokens = (const float*)d_in[7];
    const float* lp_nq      = (const float*)d_in[8];
    const float* lp_nk      = (const float*)d_in[9];
    const float* lat_to_w   = (const float*)d_in[10];
    const float* lat_from_w = (const float*)d_in[11];
    const float* mem_tokens = (const float*)d_in[12];
    const float* mem_nq     = (const float*)d_in[13];
    const float* mem_nk     = (const float*)d_in[14];
    const float* mem_read_w = (const float*)d_in[15];
    const float* mem_write_w= (const float*)d_in[16];
    const float* gate_w     = (const float*)d_in[17];
    const float* gate_b     = (const float*)d_in[18];
    const float* up_w       = (const float*)d_in[19];
    const float* down_w     = (const float*)d_in[20];
    float* out = (float*)d_out;

    cudaFuncSetAttribute(fattn, cudaFuncAttributeMaxDynamicSharedMemorySize, ATTN_SMEM);
    cudaFuncSetAttribute(gemm128, cudaFuncAttributeMaxDynamicSharedMemorySize, GEMM_SMEM);

    float* hB   = SYMF(g_h);
    float* qnB  = SYMF(g_qn);
    float* knB  = SYMF(g_kn);
    float* QB   = SYMF(g_Q);
    float* KVB  = SYMF(g_KV);
    float* OB   = SYMF(g_O);
    float* oLB  = SYMF(g_oL);
    float* oDB  = SYMF(g_oD);
    float* xlatB= SYMF(g_xlat);
    float* xmemB= SYMF(g_xmem);
    float* x1B  = SYMF(g_x1);
    float* hnB  = SYMF(g_hn);
    float* latprevB = SYMF(g_latprev);
    float* latB  = SYMF(g_lat);
    float* latqB = SYMF(g_latq);
    float* latkB = SYMF(g_latk);
    float* memprevB = SYMF(g_memprev);
    float* memB  = SYMF(g_mem);
    float* memqB = SYMF(g_memq);
    float* memkB = SYMF(g_memk);
    float* memdB = SYMF(g_memdelta);
    float* uB    = SYMF(g_u);
    float* gactB = SYMF(g_gact);
    float* partB = SYMF(g_part);

    const int rowsBL = Bdim * Ldim;

    rmsnorm_k<<<rowsBL, 256>>>(x, norm_w, hB);

    // local + dilated branches (shared q/k norms)
    rmsnorm_k<<<rowsBL, 256>>>(hB, ld_nq, qnB);
    rmsnorm_k<<<rowsBL, 256>>>(hB, ld_nk, knB);
    run_mha(qnB, knB, local_w, Ldim, Ldim, 1, kpm, nullptr, oLB, QB, KVB, OB, partB);
    run_mha(qnB, knB, dil_w,   Ldim, Ldim, 2, kpm, nullptr, oDB, QB, KVB, OB, partB);

    // latent pool
    broadcast_k<<<(BKD+255)/256, 256>>>(lat_tokens, latprevB, KLAT*Ddim, BKD);
    rmsnorm_k<<<Bdim*KLAT, 256>>>(latprevB, lp_nq, latqB);
    rmsnorm_k<<<rowsBL, 256>>>(hB, lp_nk, knB);
    run_mha(latqB, knB, lat_to_w, KLAT, Ldim, 0, kpm, latprevB, latB, QB, KVB, OB, partB);
    rmsnorm_k<<<rowsBL, 256>>>(hB, lp_nq, qnB);
    rmsnorm_k<<<Bdim*KLAT, 256>>>(latB, lp_nk, latkB);
    run_mha(qnB, latkB, lat_from_w, Ldim, KLAT, 0, nullptr, hB, xlatB, QB, KVB, OB, partB);

    // infini-memory
    broadcast_k<<<(BMD+255)/256, 256>>>(mem_tokens, memprevB, MMEM*Ddim, BMD);
    rmsnorm_k<<<Bdim*MMEM, 256>>>(memprevB, mem_nq, memqB);
    rmsnorm_k<<<rowsBL, 256>>>(hB, mem_nk, knB);
    run_mha(memqB, knB, mem_write_w, MMEM, Ldim, 0, kpm, nullptr, memdB, QB, KVB, OB, partB);
    ema_k<<<(BMD+255)/256, 256>>>(memprevB, memdB, memB, BMD);
    rmsnorm_k<<<rowsBL, 256>>>(hB, mem_nq, qnB);
    rmsnorm_k<<<Bdim*MMEM, 256>>>(memB, mem_nk, memkB);
    run_mha(qnB, memkB, mem_read_w, Ldim, MMEM, 0, nullptr, hB, xmemB, QB, KVB, OB, partB);

    // gated fusion
    gate_fuse<<<rowsBL, 128>>>(x, hB, oLB, oDB, xlatB, xmemB, gate_w, gate_b, x1B);

    // SwiGLU FFN
    rmsnorm_k<<<rowsBL, 256>>>(x1B, norm_w, hnB);
    gemm128<<<dim3(2*DFFdim/128, rowsBL/128, 1), 256, GEMM_SMEM>>>(hnB, up_w, nullptr, uB,
                                                        rowsBL, 2*DFFdim, Ddim, Ddim);
    int nact = rowsBL * DFFdim;
    silu_mul_k<<<(nact+255)/256, 256>>>(uB, gactB, nact);
    // down proj split-K=2 for full-chip fill
    gemm128<<<dim3(Ddim/128, rowsBL/128, 2), 256, GEMM_SMEM>>>(gactB, down_w, nullptr, partB,
                                                    rowsBL, Ddim, DFFdim, DFFdim/2);
    reduce_splitk<<<(BLD+255)/256, 256>>>(partB, x1B, out, BLD, 2);

    // lat + mem outputs
    copy_k<<<(BKD+255)/256, 256>>>(latB, out + (size_t)BLD, BKD);
    copy_k<<<(BMD+255)/256, 256>>>(memB, out + (size_t)BLD + BKD, BMD);
}

// round 5
// speedup vs baseline: 6.6476x; 1.1900x over previous
#include <cuda_runtime.h>
#include <math.h>
#include <stdint.h>

#define Bdim 2
#define Ldim 1024
#define Ddim 1024
#define Hdim 16
#define HDdim 64
#define DFFdim 4096
#define WINv 128
#define DILv 4
#define KLAT 64
#define MMEM 64
#define EPSV 1e-6f

#define BLD (Bdim*Ldim*Ddim)
#define BKD (Bdim*KLAT*Ddim)
#define BMD (Bdim*MMEM*Ddim)

// ---------------- scratch (static device memory; no allocations) -------------
__device__ float g_h[BLD];
__device__ float g_qn[BLD];
__device__ float g_kn[BLD];
__device__ float g_qn2[BLD];
__device__ float g_kn2[BLD];
__device__ float g_qn3[BLD];
__device__ float g_kn3[BLD];
__device__ float g_Qa[BLD];
__device__ float g_KVa[(size_t)Bdim*Ldim*2*Ddim];
__device__ float g_Oa[BLD];
__device__ float g_parta[(size_t)2048*1024*2];
__device__ float g_Qb[BLD];
__device__ float g_KVb[(size_t)Bdim*Ldim*2*Ddim];
__device__ float g_Ob[BLD];
__device__ float g_partb[(size_t)2048*1024*2];
__device__ float g_oL[BLD];
__device__ float g_oD[BLD];
__device__ float g_xlat[BLD];
__device__ float g_xmem[BLD];
__device__ float g_x1[BLD];
__device__ float g_hn[BLD];
__device__ float g_latprev[BKD];
__device__ float g_lat[BKD];
__device__ float g_latq[BKD];
__device__ float g_latk[BKD];
__device__ float g_memprev[BMD];
__device__ float g_mem[BMD];
__device__ float g_memq[BMD];
__device__ float g_memk[BMD];
__device__ float g_memdelta[BMD];
__device__ float g_u[(size_t)Bdim*Ldim*2*DFFdim];
__device__ float g_gact[(size_t)Bdim*Ldim*DFFdim];

// ---------------- rmsnorm ----------------------------------------------------
__global__ void rmsnorm_k(const float* __restrict__ x, const float* __restrict__ w,
                          float* __restrict__ o) {
    int row = blockIdx.x;
    const float* xr = x + (size_t)row * Ddim;
    float* orow = o + (size_t)row * Ddim;
    int tid = threadIdx.x;          // 256 threads
    float v[4];
    float s = 0.f;
#pragma unroll
    for (int i = 0; i < 4; i++) { v[i] = xr[tid + i*256]; s += v[i]*v[i]; }
    __shared__ float red[8];
#pragma unroll
    for (int off = 16; off; off >>= 1) s += __shfl_xor_sync(0xffffffffu, s, off);
    if ((tid & 31) == 0) red[tid >> 5] = s;
    __syncthreads();
    float tot = 0.f;
#pragma unroll
    for (int i = 0; i < 8; i++) tot += red[i];
    float scale = rsqrtf(tot * (1.0f/Ddim) + EPSV);
#pragma unroll
    for (int i = 0; i < 4; i++) orow[tid + i*256] = w[tid + i*256] * (v[i] * scale);
}

// ---------------- tf32 mma helpers -------------------------------------------
__device__ __forceinline__ uint32_t f2tf(float f) {
    uint32_t u;
    asm("cvt.rna.tf32.f32 %0, %1;" : "=r"(u) : "f"(f));
    return u;
}
__device__ __forceinline__ void mma_tf32(float* c, const uint32_t* a, const uint32_t* b) {
    asm volatile("mma.sync.aligned.m16n8k8.row.col.f32.tf32.tf32.f32 "
        "{%0,%1,%2,%3}, {%4,%5,%6,%7}, {%8,%9}, {%0,%1,%2,%3};"
        : "+f"(c[0]), "+f"(c[1]), "+f"(c[2]), "+f"(c[3])
        : "r"(a[0]), "r"(a[1]), "r"(a[2]), "r"(a[3]), "r"(b[0]), "r"(b[1]));
}
__device__ __forceinline__ void cp16(uint32_t dst, const void* src) {
    asm volatile("cp.async.cg.shared.global [%0], [%1], 16;" :: "r"(dst), "l"(src));
}
__device__ __forceinline__ void cp_commit() {
    asm volatile("cp.async.commit_group;");
}
template <int N>
__device__ __forceinline__ void cp_wait() {
    asm volatile("cp.async.wait_group %0;" :: "n"(N));
}

// ---------------- GEMM 128x128, 256 thr, cp.async 3-stage --------------------
#define GSTAGE 3
#define GTILEF (128*20)
#define GEMM_SMEM (GSTAGE*GTILEF*2*4)
__global__ void __launch_bounds__(256, 2) gemm128(
    const float* __restrict__ A, const float* __restrict__ Bm,
    const float* __restrict__ res, float* __restrict__ C,
    int M, int N, int K, int Kc) {
    extern __shared__ float smg[];
    float* As = smg;
    float* Bs = smg + GSTAGE*GTILEF;
    int tid = threadIdx.x, lane = tid & 31, wid = tid >> 5;
    int bm = blockIdx.y * 128, bn = blockIdx.x * 128;
    int wm = (wid & 1) * 64, wn = (wid >> 1) * 32;
    int k0base = blockIdx.z * Kc;
    float* Cw = C + (size_t)blockIdx.z * M * N;

    int lrow = tid >> 1;
    int lkq  = (tid & 1) * 8;
    const float* Ag = A + (size_t)(bm + lrow) * K + k0base + lkq;
    const float* Bg = Bm + (size_t)(bn + lrow) * K + k0base + lkq;
    uint32_t sA = (uint32_t)__cvta_generic_to_shared(As) + (lrow*20 + lkq)*4;
    uint32_t sB = (uint32_t)__cvta_generic_to_shared(Bs) + (lrow*20 + lkq)*4;

    float c[4][4][4] = {};
    int ntiles = Kc >> 4;

    {
        cp16(sA, Ag); cp16(sA + 16, Ag + 4);
        cp16(sB, Bg); cp16(sB + 16, Bg + 4);
        cp_commit();
        if (ntiles > 1) {
            cp16(sA + GTILEF*4, Ag + 16); cp16(sA + GTILEF*4 + 16, Ag + 20);
            cp16(sB + GTILEF*4, Bg + 16); cp16(sB + GTILEF*4 + 16, Bg + 20);
        }
        cp_commit();
    }

    for (int kt = 0; kt < ntiles; kt++) {
        cp_wait<1>();
        __syncthreads();
        if (kt + 2 < ntiles) {
            int s = (kt + 2) % GSTAGE;
            const float* Ap = Ag + (size_t)(kt+2)*16;
            const float* Bp = Bg + (size_t)(kt+2)*16;
            cp16(sA + s*GTILEF*4, Ap); cp16(sA + s*GTILEF*4 + 16, Ap + 4);
            cp16(sB + s*GTILEF*4, Bp); cp16(sB + s*GTILEF*4 + 16, Bp + 4);
        }
        cp_commit();

        const float* Ac = As + (kt % GSTAGE) * GTILEF;
        const float* Bc = Bs + (kt % GSTAGE) * GTILEF;
#pragma unroll
        for (int ks = 0; ks < 2; ks++) {
            int kb = ks*8 + (lane & 3);
            int rA = wm + (lane >> 2);
            int rB = wn + (lane >> 2);
            uint32_t a[4][4], b[4][2];
#pragma unroll
            for (int mt = 0; mt < 4; mt++) {
                a[mt][0] = __float_as_uint(Ac[(rA + mt*16    )*20 + kb]);
                a[mt][1] = __float_as_uint(Ac[(rA + mt*16 + 8)*20 + kb]);
                a[mt][2] = __float_as_uint(Ac[(rA + mt*16    )*20 + kb+4]);
                a[mt][3] = __float_as_uint(Ac[(rA + mt*16 + 8)*20 + kb+4]);
            }
#pragma unroll
            for (int nt = 0; nt < 4; nt++) {
                b[nt][0] = __float_as_uint(Bc[(rB + nt*8)*20 + kb]);
                b[nt][1] = __float_as_uint(Bc[(rB + nt*8)*20 + kb+4]);
            }
#pragma unroll
            for (int mt = 0; mt < 4; mt++)
#pragma unroll
                for (int nt = 0; nt < 4; nt++)
                    mma_tf32(c[mt][nt], a[mt], b[nt]);
        }
        __syncthreads();
    }

#pragma unroll
    for (int mt = 0; mt < 4; mt++) {
        int r0 = bm + wm + mt*16 + (lane >> 2);
#pragma unroll
        for (int nt = 0; nt < 4; nt++) {
            int cc = bn + wn + nt*8 + (lane & 3)*2;
            float2 v0 = make_float2(c[mt][nt][0], c[mt][nt][1]);
            float2 v1 = make_float2(c[mt][nt][2], c[mt][nt][3]);
            if (res) {
                float2 q0 = *reinterpret_cast<const float2*>(&res[(size_t)r0*N + cc]);
                float2 q1 = *reinterpret_cast<const float2*>(&res[(size_t)(r0+8)*N + cc]);
                v0.x += q0.x; v0.y += q0.y; v1.x += q1.x; v1.y += q1.y;
            }
            *reinterpret_cast<float2*>(&Cw[(size_t)r0*N + cc]) = v0;
            *reinterpret_cast<float2*>(&Cw[(size_t)(r0+8)*N + cc]) = v1;
        }
    }
}

// ---------------- GEMM 64x64, 128 thr, split-K -------------------------------
__global__ void __launch_bounds__(128) gemm64(
    const float* __restrict__ A, const float* __restrict__ Bm,
    float* __restrict__ C, int M, int N, int K, int Kc) {
    __shared__ uint32_t As[2][64][20];
    __shared__ uint32_t Bs[2][64][20];
    int tid = threadIdx.x, lane = tid & 31, wid = tid >> 5;
    int bm = blockIdx.y * 64, bn = blockIdx.x * 64;
    int wm = (wid & 1) * 32, wn = (wid >> 1) * 32;
    int k0base = blockIdx.z * Kc;
    float* Cw = C + (size_t)blockIdx.z * M * N;

    int lrow = tid >> 1;
    int lkq  = (tid & 1) * 8;
    const float* Ag = A + (size_t)(bm + lrow) * K + k0base + lkq;
    const float* Bg = Bm + (size_t)(bn + lrow) * K + k0base + lkq;

    float c[2][4][4] = {};
    int ntiles = Kc >> 4;

    float4 la0, la1, lb0, lb1;
    la0 = *reinterpret_cast<const float4*>(Ag);
    la1 = *reinterpret_cast<const float4*>(Ag + 4);
    lb0 = *reinterpret_cast<const float4*>(Bg);
    lb1 = *reinterpret_cast<const float4*>(Bg + 4);
    As[0][lrow][lkq+0] = f2tf(la0.x); As[0][lrow][lkq+1] = f2tf(la0.y);
    As[0][lrow][lkq+2] = f2tf(la0.z); As[0][lrow][lkq+3] = f2tf(la0.w);
    As[0][lrow][lkq+4] = f2tf(la1.x); As[0][lrow][lkq+5] = f2tf(la1.y);
    As[0][lrow][lkq+6] = f2tf(la1.z); As[0][lrow][lkq+7] = f2tf(la1.w);
    Bs[0][lrow][lkq+0] = f2tf(lb0.x); Bs[0][lrow][lkq+1] = f2tf(lb0.y);
    Bs[0][lrow][lkq+2] = f2tf(lb0.z); Bs[0][lrow][lkq+3] = f2tf(lb0.w);
    Bs[0][lrow][lkq+4] = f2tf(lb1.x); Bs[0][lrow][lkq+5] = f2tf(lb1.y);
    Bs[0][lrow][lkq+6] = f2tf(lb1.z); Bs[0][lrow][lkq+7] = f2tf(lb1.w);
    __syncthreads();

    for (int kt = 0; kt < ntiles; kt++) {
        int cur = kt & 1;
        if (kt + 1 < ntiles) {
            const float* Ap = Ag + (size_t)(kt+1)*16;
            const float* Bp = Bg + (size_t)(kt+1)*16;
            la0 = *reinterpret_cast<const float4*>(Ap);
            la1 = *reinterpret_cast<const float4*>(Ap + 4);
            lb0 = *reinterpret_cast<const float4*>(Bp);
            lb1 = *reinterpret_cast<const float4*>(Bp + 4);
        }
#pragma unroll
        for (int ks = 0; ks < 2; ks++) {
            int kb = ks*8 + (lane & 3);
            int rA = wm + (lane >> 2);
            int rB = wn + (lane >> 2);
            uint32_t a[2][4], b[4][2];
#pragma unroll
            for (int mt = 0; mt < 2; mt++) {
                a[mt][0] = As[cur][rA + mt*16    ][kb];
                a[mt][1] = As[cur][rA + mt*16 + 8][kb];
                a[mt][2] = As[cur][rA + mt*16    ][kb+4];
                a[mt][3] = As[cur][rA + mt*16 + 8][kb+4];
            }
#pragma unroll
            for (int nt = 0; nt < 4; nt++) {
                b[nt][0] = Bs[cur][rB + nt*8][kb];
                b[nt][1] = Bs[cur][rB + nt*8][kb+4];
            }
#pragma unroll
            for (int mt = 0; mt < 2; mt++)
#pragma unroll
                for (int nt = 0; nt < 4; nt++)
                    mma_tf32(c[mt][nt], a[mt], b[nt]);
        }
        if (kt + 1 < ntiles) {
            int nxt = cur ^ 1;
            As[nxt][lrow][lkq+0] = f2tf(la0.x); As[nxt][lrow][lkq+1] = f2tf(la0.y);
            As[nxt][lrow][lkq+2] = f2tf(la0.z); As[nxt][lrow][lkq+3] = f2tf(la0.w);
            As[nxt][lrow][lkq+4] = f2tf(la1.x); As[nxt][lrow][lkq+5] = f2tf(la1.y);
            As[nxt][lrow][lkq+6] = f2tf(la1.z); As[nxt][lrow][lkq+7] = f2tf(la1.w);
            Bs[nxt][lrow][lkq+0] = f2tf(lb0.x); Bs[nxt][lrow][lkq+1] = f2tf(lb0.y);
            Bs[nxt][lrow][lkq+2] = f2tf(lb0.z); Bs[nxt][lrow][lkq+3] = f2tf(lb0.w);
            Bs[nxt][lrow][lkq+4] = f2tf(lb1.x); Bs[nxt][lrow][lkq+5] = f2tf(lb1.y);
            Bs[nxt][lrow][lkq+6] = f2tf(lb1.z); Bs[nxt][lrow][lkq+7] = f2tf(lb1.w);
        }
        __syncthreads();
    }

#pragma unroll
    for (int mt = 0; mt < 2; mt++) {
        int r0 = bm + wm + mt*16 + (lane >> 2);
#pragma unroll
        for (int nt = 0; nt < 4; nt++) {
            int cc = bn + wn + nt*8 + (lane & 3)*2;
            *reinterpret_cast<float2*>(&Cw[(size_t)r0*N + cc]) =
                make_float2(c[mt][nt][0], c[mt][nt][1]);
            *reinterpret_cast<float2*>(&Cw[(size_t)(r0+8)*N + cc]) =
                make_float2(c[mt][nt][2], c[mt][nt][3]);
        }
    }
}

// ---------------- split-K reduce ----------------------------------------------
__global__ void reduce_splitk(const float* __restrict__ part, const float* __restrict__ res,
                              float* __restrict__ out, int MN, int SK) {
    int i = blockIdx.x*256 + threadIdx.x;
    if (i >= MN) return;
    float s = res ? res[i] : 0.f;
    for (int k = 0; k < SK; k++) s += part[(size_t)k*MN + i];
    out[i] = s;
}

// ---------------- fused flash attention --------------------------------------
#define ATTN_SMEM (4*64*68*4 + 3*64*4)
__global__ void __launch_bounds__(256) fattn(
    const float* __restrict__ Q, const float* __restrict__ Kg,
    const float* __restrict__ Vg, float* __restrict__ O,
    int lq, int lk, int ldk, int mask_mode, const unsigned char* __restrict__ kpm) {
    extern __shared__ float sm[];
    float (*Qs)[68] = (float(*)[68])sm;
    float (*Ks)[68] = (float(*)[68])(sm + 64*68);
    float (*Vs)[68] = (float(*)[68])(sm + 2*64*68);
    float (*Ps)[68] = (float(*)[68])(sm + 3*64*68);
    float* m_s  = sm + 4*64*68;
    float* l_s  = m_s + 64;
    float* al_s = l_s + 64;

    int tid = threadIdx.x;
    int q0 = blockIdx.x * 64;
    int bh = blockIdx.y;
    int b = bh >> 4, h = bh & 15;

#pragma unroll
    for (int i = 0; i < 4; i++) {
        int id = tid + i*256;
        int r = id >> 4, dq = (id & 15) * 4;
        *reinterpret_cast<float4*>(&Qs[r][dq]) =
            *reinterpret_cast<const float4*>(&Q[((size_t)(b*lq + q0 + r))*Ddim + h*HDdim + dq]);
    }
    if (tid < 64) { m_s[tid] = -INFINITY; l_s[tid] = 0.f; }
    __syncthreads();

    int ty = tid >> 4, tx = tid & 15;
    int r0 = ty * 4;
    float o[4][4] = {};

    int c_lo = 0, c_hi = lk >> 6;
    if (mask_mode) {
        c_lo = (q0 >= WINv) ? (q0 - WINv) >> 6 : 0;
        int hi = (q0 + 64 + WINv) >> 6;
        if (hi < c_hi) c_hi = hi;
    }

    for (int ck = c_lo; ck < c_hi; ck++) {
        int kb = ck * 64;
#pragma unroll
        for (int i = 0; i < 4; i++) {
            int id = tid + i*256;
            int r = id >> 4, dq = (id & 15)*4;
            size_t g = ((size_t)(b*lk + kb + r))*ldk + h*HDdim + dq;
            *reinterpret_cast<float4*>(&Ks[r][dq]) = *reinterpret_cast<const float4*>(&Kg[g]);
            *reinterpret_cast<float4*>(&Vs[r][dq]) = *reinterpret_cast<const float4*>(&Vg[g]);
        }
        __syncthreads();

        float s[4][4] = {};
#pragma unroll
        for (int k = 0; k < 64; k += 4) {
            float4 qv[4], kv[4];
#pragma unroll
            for (int i = 0; i < 4; i++) qv[i] = *reinterpret_cast<float4*>(&Qs[r0+i][k]);
#pragma unroll
            for (int j = 0; j < 4; j++) kv[j] = *reinterpret_cast<float4*>(&Ks[tx + 16*j][k]);
#pragma unroll
            for (int i = 0; i < 4; i++)
#pragma unroll
                for (int j = 0; j < 4; j++)
                    s[i][j] += qv[i].x*kv[j].x + qv[i].y*kv[j].y
                             + qv[i].z*kv[j].z + qv[i].w*kv[j].w;
        }
#pragma unroll
        for (int i = 0; i < 4; i++) {
            int qr = q0 + r0 + i;
#pragma unroll
            for (int j = 0; j < 4; j++) {
                int col = kb + tx + 16*j;
                float v = s[i][j] * 0.125f;
                int jr = col - qr;
                bool ok = true;
                if (mask_mode == 1) ok = (jr <= WINv && jr >= -WINv);
                else if (mask_mode == 2) ok = (jr <= WINv && jr >= -WINv && ((jr & 3) == 0));
                if (kpm && kpm[b*lk + col]) ok = false;
                Ps[r0+i][tx + 16*j] = ok ? v : -INFINITY;
            }
        }
        __syncthreads();

        {
            int w = tid >> 5, ln = tid & 31;
            for (int rr = w*8; rr < w*8 + 8; rr++) {
                float s0 = Ps[rr][ln], s1 = Ps[rr][ln+32];
                float mx = fmaxf(s0, s1);
#pragma unroll
                for (int off = 16; off; off >>= 1)
                    mx = fmaxf(mx, __shfl_xor_sync(0xffffffffu, mx, off));
                float mo = m_s[rr];
                float mn = fmaxf(mo, mx);
                float p0, p1, alpha;
                if (mn == -INFINITY) { p0 = 0.f; p1 = 0.f; alpha = 1.f; }
                else {
                    alpha = __expf(mo - mn);
                    p0 = (s0 == -INFINITY) ? 0.f : __expf(s0 - mn);
                    p1 = (s1 == -INFINITY) ? 0.f : __expf(s1 - mn);
                }
                Ps[rr][ln] = p0; Ps[rr][ln+32] = p1;
                float sum = p0 + p1;
#pragma unroll
                for (int off = 16; off; off >>= 1)
                    sum += __shfl_xor_sync(0xffffffffu, sum, off);
                if (ln == 0) {
                    l_s[rr] = l_s[rr]*alpha + sum;
                    m_s[rr] = mn;
                    al_s[rr] = alpha;
                }
            }
        }
        __syncthreads();

#pragma unroll
        for (int i = 0; i < 4; i++) {
            float a = al_s[r0+i];
#pragma unroll
            for (int j = 0; j < 4; j++) o[i][j] *= a;
        }
#pragma unroll
        for (int k = 0; k < 64; k += 4) {
            float4 pk[4];
#pragma unroll
            for (int i = 0; i < 4; i++) pk[i] = *reinterpret_cast<float4*>(&Ps[r0+i][k]);
#pragma unroll
            for (int kk = 0; kk < 4; kk++) {
                float4 vv = *reinterpret_cast<float4*>(&Vs[k+kk][tx*4]);
#pragma unroll
                for (int i = 0; i < 4; i++) {
                    float p = (kk == 0) ? pk[i].x : (kk == 1) ? pk[i].y : (kk == 2) ? pk[i].z : pk[i].w;
                    o[i][0] += p*vv.x; o[i][1] += p*vv.y; o[i][2] += p*vv.z; o[i][3] += p*vv.w;
                }
            }
        }
        __syncthreads();
    }

#pragma unroll
    for (int i = 0; i < 4; i++) {
        float inv = 1.0f / l_s[r0+i];
        float4 ov = make_float4(o[i][0]*inv, o[i][1]*inv, o[i][2]*inv, o[i][3]*inv);
        *reinterpret_cast<float4*>(&O[((size_t)(b*lq + q0 + r0 + i))*Ddim + h*HDdim + tx*4]) = ov;
    }
}

// ---------------- gated fusion -----------------------------------------------
__global__ void gate_fuse(const float* __restrict__ x, const float* __restrict__ h,
                          const float* __restrict__ o0, const float* __restrict__ o1,
                          const float* __restrict__ o2, const float* __restrict__ o3,
                          const float* __restrict__ gw, const float* __restrict__ gb,
                          float* __restrict__ out) {
    int row = blockIdx.x;
    int tid = threadIdx.x; // 128
    int warp = tid >> 5, lane = tid & 31;
    __shared__ float wsh[4];
    const float* hr = h + (size_t)row * Ddim;
    float p = 0.f;
    const float* gwr = gw + warp * Ddim;
    for (int dd = lane; dd < Ddim; dd += 32) p += hr[dd] * gwr[dd];
#pragma unroll
    for (int off = 16; off; off >>= 1) p += __shfl_down_sync(0xffffffffu, p, off);
    if (lane == 0) wsh[warp] = p + gb[warp];
    __syncthreads();
    if (tid == 0) {
        float mx = fmaxf(fmaxf(wsh[0], wsh[1]), fmaxf(wsh[2], wsh[3]));
        float e0 = expf(wsh[0]-mx), e1 = expf(wsh[1]-mx), e2 = expf(wsh[2]-mx), e3 = expf(wsh[3]-mx);
        float inv = 1.0f / (e0+e1+e2+e3);
        wsh[0] = e0*inv; wsh[1] = e1*inv; wsh[2] = e2*inv; wsh[3] = e3*inv;
    }
    __syncthreads();
    float w0 = wsh[0], w1 = wsh[1], w2 = wsh[2], w3 = wsh[3];
    size_t base = (size_t)row * Ddim;
    for (int dd = tid; dd < Ddim; dd += 128)
        out[base+dd] = x[base+dd] + w0*o0[base+dd] + w1*o1[base+dd]
                                  + w2*o2[base+dd] + w3*o3[base+dd];
}

// ---------------- elementwise helpers ----------------------------------------
__global__ void broadcast_k(const float* __restrict__ src, float* __restrict__ dst,
                            int mask, int total) {
    int i = blockIdx.x*256 + threadIdx.x;
    if (i < total) dst[i] = src[i & mask];
}
__global__ void ema_k(const float* __restrict__ prev, const float* __restrict__ delta,
                      float* __restrict__ mem, int n) {
    int i = blockIdx.x*256 + threadIdx.x;
    if (i < n) mem[i] = 0.9f*prev[i] + 0.1f*(prev[i] + delta[i]);
}
__global__ void silu_mul_k(const float* __restrict__ u, float* __restrict__ o, int n) {
    int i = blockIdx.x*256 + threadIdx.x;
    if (i < n) {
        int r = i >> 12, f = i & (DFFdim - 1);
        float a = u[((size_t)r << 13) + f];
        float g = u[((size_t)r << 13) + DFFdim + f];
        o[i] = (a / (1.0f + expf(-a))) * g;
    }
}
__global__ void copy_k(const float* __restrict__ src, float* __restrict__ dst, int n) {
    int i = blockIdx.x*256 + threadIdx.x;
    if (i < n) dst[i] = src[i];
}

#define SYMF(name) ({ void* _p = nullptr; cudaGetSymbolAddress(&_p, name); (float*)_p; })

// generic projection: C[M,N] = A @ W^T (+res); picks path by shape
static void proj(const float* A, const float* W, const float* res, float* C,
                 float* partB, int M, int N, int K, cudaStream_t st) {
    if (M >= 1024) {
        if (N == 1024 && K >= 512) {
            gemm128<<<dim3(N/128, M/128, 2), 256, GEMM_SMEM, st>>>(A, W, nullptr, partB, M, N, K, K/2);
            reduce_splitk<<<(M*N+255)/256, 256, 0, st>>>(partB, res, C, M*N, 2);
        } else {
            gemm128<<<dim3(N/128, M/128, 1), 256, GEMM_SMEM, st>>>(A, W, res, C, M, N, K, K);
        }
    } else {
        const int SK = 4;
        gemm64<<<dim3(N/64, M/64, SK), 128, 0, st>>>(A, W, partB, M, N, K, K/SK);
        int MN = M*N;
        reduce_splitk<<<(MN+255)/256, 256, 0, st>>>(partB, res, C, MN, SK);
    }
}

static void run_mha(const float* qin, const float* kvin, const float* w,
                    int lq, int lk, int mask_mode, const unsigned char* kpm,
                    const float* res, float* out,
                    float* Qb, float* KVb, float* Ob, float* partB, cudaStream_t st) {
    const float* Wq = w;
    const float* Wkv = w + Ddim*Ddim;
    const float* Wo = w + 3*Ddim*Ddim;
    int Mq = Bdim * lq, Mk = Bdim * lk;
    proj(qin, Wq, nullptr, Qb, partB, Mq, Ddim, Ddim, st);
    proj(kvin, Wkv, nullptr, KVb, partB, Mk, 2*Ddim, Ddim, st);
    fattn<<<dim3(lq/64, Bdim*Hdim), 256, ATTN_SMEM, st>>>(Qb, KVb, KVb + Ddim, Ob,
                                                          lq, lk, 2*Ddim, mask_mode, kpm);
    proj(Ob, Wo, res, out, partB, Mq, Ddim, Ddim, st);
}

extern "C" void kernel_launch(void* const* d_in, const int* in_sizes, int n_in,
                              void* d_out, int out_size) {
    const float* x          = (const float*)d_in[0];
    const unsigned char* kpm = (const unsigned char*)d_in[1];
    const float* norm_w     = (const float*)d_in[2];
    const float* ld_nq      = (const float*)d_in[3];
    const float* ld_nk      = (const float*)d_in[4];
    const float* local_w    = (const float*)d_in[5];
    const float* dil_w      = (const float*)d_in[6];
    const float* lat_tokens = (const float*)d_in[7];
    const float* lp_nq      = (const float*)d_in[8];
    const float* lp_nk      = (const float*)d_in[9];
    const float* lat_to_w   = (const float*)d_in[10];
    const float* lat_from_w = (const float*)d_in[11];
    const float* mem_tokens = (const float*)d_in[12];
    const float* mem_nq     = (const float*)d_in[13];
    const float* mem_nk     = (const float*)d_in[14];
    const float* mem_read_w = (const float*)d_in[15];
    const float* mem_write_w= (const float*)d_in[16];
    const float* gate_w     = (const float*)d_in[17];
    const float* gate_b     = (const float*)d_in[18];
    const float* up_w       = (const float*)d_in[19];
    const float* down_w     = (const float*)d_in[20];
    float* out = (float*)d_out;

    // one-time resources (no device memory involved)
    static cudaStream_t sA = nullptr, sB = nullptr;
    static cudaEvent_t evFork = nullptr, evA = nullptr, evB = nullptr;
    if (!sA) {
        cudaStreamCreateWithFlags(&sA, cudaStreamNonBlocking);
        cudaStreamCreateWithFlags(&sB, cudaStreamNonBlocking);
        cudaEventCreateWithFlags(&evFork, cudaEventDisableTiming);
        cudaEventCreateWithFlags(&evA, cudaEventDisableTiming);
        cudaEventCreateWithFlags(&evB, cudaEventDisableTiming);
        cudaFuncSetAttribute(fattn, cudaFuncAttributeMaxDynamicSharedMemorySize, ATTN_SMEM);
        cudaFuncSetAttribute(gemm128, cudaFuncAttributeMaxDynamicSharedMemorySize, GEMM_SMEM);
    }

    float* hB   = SYMF(g_h);
    float* qnB  = SYMF(g_qn);
    float* knB  = SYMF(g_kn);
    float* qn2B = SYMF(g_qn2);
    float* kn2B = SYMF(g_kn2);
    float* qn3B = SYMF(g_qn3);
    float* kn3B = SYMF(g_kn3);
    float* QaB  = SYMF(g_Qa);
    float* KVaB = SYMF(g_KVa);
    float* OaB  = SYMF(g_Oa);
    float* partaB = SYMF(g_parta);
    float* QbB  = SYMF(g_Qb);
    float* KVbB = SYMF(g_KVb);
    float* ObB  = SYMF(g_Ob);
    float* partbB = SYMF(g_partb);
    float* oLB  = SYMF(g_oL);
    float* oDB  = SYMF(g_oD);
    float* xlatB= SYMF(g_xlat);
    float* xmemB= SYMF(g_xmem);
    float* x1B  = SYMF(g_x1);
    float* hnB  = SYMF(g_hn);
    float* latprevB = SYMF(g_latprev);
    float* latB  = SYMF(g_lat);
    float* latqB = SYMF(g_latq);
    float* latkB = SYMF(g_latk);
    float* memprevB = SYMF(g_memprev);
    float* memB  = SYMF(g_mem);
    float* memqB = SYMF(g_memq);
    float* memkB = SYMF(g_memk);
    float* memdB = SYMF(g_memdelta);
    float* uB    = SYMF(g_u);
    float* gactB = SYMF(g_gact);

    const int rowsBL = Bdim * Ldim;

    // shared prologue on the capture (default) stream
    rmsnorm_k<<<rowsBL, 256>>>(x, norm_w, hB);
    rmsnorm_k<<<rowsBL, 256>>>(hB, ld_nq, qnB);
    rmsnorm_k<<<rowsBL, 256>>>(hB, ld_nk, knB);
    cudaEventRecord(evFork, 0);
    cudaStreamWaitEvent(sA, evFork, 0);
    cudaStreamWaitEvent(sB, evFork, 0);

    // ---- stream A: local branch, then latent chain ----
    run_mha(qnB, knB, local_w, Ldim, Ldim, 1, kpm, nullptr, oLB, QaB, KVaB, OaB, partaB, sA);

    broadcast_k<<<(BKD+255)/256, 256, 0, sA>>>(lat_tokens, latprevB, KLAT*Ddim - 1, BKD);
    rmsnorm_k<<<Bdim*KLAT, 256, 0, sA>>>(latprevB, lp_nq, latqB);
    rmsnorm_k<<<rowsBL, 256, 0, sA>>>(hB, lp_nk, kn2B);
    run_mha(latqB, kn2B, lat_to_w, KLAT, Ldim, 0, kpm, latprevB, latB, QaB, KVaB, OaB, partaB, sA);
    rmsnorm_k<<<rowsBL, 256, 0, sA>>>(hB, lp_nq, qn2B);
    rmsnorm_k<<<Bdim*KLAT, 256, 0, sA>>>(latB, lp_nk, latkB);
    run_mha(qn2B, latkB, lat_from_w, Ldim, KLAT, 0, nullptr, hB, xlatB, QaB, KVaB, OaB, partaB, sA);
    copy_k<<<(BKD+255)/256, 256, 0, sA>>>(latB, out + (size_t)BLD, BKD);
    cudaEventRecord(evA, sA);

    // ---- stream B: dilated branch, then memory chain ----
    run_mha(qnB, knB, dil_w, Ldim, Ldim, 2, kpm, nullptr, oDB, QbB, KVbB, ObB, partbB, sB);

    broadcast_k<<<(BMD+255)/256, 256, 0, sB>>>(mem_tokens, memprevB, MMEM*Ddim - 1, BMD);
    rmsnorm_k<<<Bdim*MMEM, 256, 0, sB>>>(memprevB, mem_nq, memqB);
    rmsnorm_k<<<rowsBL, 256, 0, sB>>>(hB, mem_nk, kn3B);
    run_mha(memqB, kn3B, mem_write_w, MMEM, Ldim, 0, kpm, nullptr, memdB, QbB, KVbB, ObB, partbB, sB);
    ema_k<<<(BMD+255)/256, 256, 0, sB>>>(memprevB, memdB, memB, BMD);
    rmsnorm_k<<<rowsBL, 256, 0, sB>>>(hB, mem_nq, qn3B);
    rmsnorm_k<<<Bdim*MMEM, 256, 0, sB>>>(memB, mem_nk, memkB);
    run_mha(qn3B, memkB, mem_read_w, Ldim, MMEM, 0, nullptr, hB, xmemB, QbB, KVbB, ObB, partbB, sB);
    copy_k<<<(BMD+255)/256, 256, 0, sB>>>(memB, out + (size_t)BLD + BKD, BMD);
    cudaEventRecord(evB, sB);

    // ---- join, then fusion + FFN on the capture stream ----
    cudaStreamWaitEvent(0, evA, 0);
    cudaStreamWaitEvent(0, evB, 0);

    gate_fuse<<<rowsBL, 128>>>(x, hB, oLB, oDB, xlatB, xmemB, gate_w, gate_b, x1B);

    rmsnorm_k<<<rowsBL, 256>>>(x1B, norm_w, hnB);
    gemm128<<<dim3(2*DFFdim/128, rowsBL/128, 1), 256, GEMM_SMEM>>>(hnB, up_w, nullptr, uB,
                                                        rowsBL, 2*DFFdim, Ddim, Ddim);
    int nact = rowsBL * DFFdim;
    silu_mul_k<<<(nact+255)/256, 256>>>(uB, gactB, nact);
    gemm128<<<dim3(Ddim/128, rowsBL/128, 2), 256, GEMM_SMEM>>>(gactB, down_w, nullptr, partaB,
                                                    rowsBL, Ddim, DFFdim, DFFdim/2);
    reduce_splitk<<<(BLD+255)/256, 256>>>(partaB, x1B, out, BLD, 2);
}